// round 8
// baseline (speedup 1.0000x reference)
#include <cuda_runtime.h>
#include <cuda_fp16.h>
#include <math.h>
#include <stdint.h>

#define N0_ 60000
#define N1_ 15000
#define N2_ 3750
#define K_  32
#define P_  15

// ---------------- intermediate buffers (device globals; no allocations) ----------
__device__ __align__(16) __half g_f1 [N0_*64];        // skip0
__device__ __align__(16) __half g_f2 [N1_*64];
__device__ __align__(16) __half g_f3 [N1_*128];       // skip1
__device__ __align__(16) __half g_f4 [N2_*128];
__device__ __align__(16) __half g_f5 [N2_*256];
__device__ __align__(16) __half g_fu1[N1_*128];
__device__ __align__(16) float  g_ff [N0_*32];
__device__ __align__(16) __half g_wh [1038336];       // all prepped half weights
__device__ float g_rowsum[N0_];
__device__ int g_gmax;

// weight offsets (halfs): conv weights permuted k=c*16+p, padded Kdp=CIN*16
#define WOFF_W2  0         // 64  x 1024
#define WOFF_W3  65536     // 128 x 1024
#define WOFF_W4  196608    // 128 x 2048
#define WOFF_W5  458752    // 256 x 2048
#define WOFF_U1  983040    // 128 x 384  (plain)
#define WOFF_U2  1032192   // 32  x 192  (plain)

// ---------------- prep: weight transposes (+ gmax reset) -------------------------
// conv weights: fp32 [p*CIN+c][N] -> half [N][k_new = c*16 + p], p=15 rows zeroed.
// unary weights: fp32 [Kd][N] -> half [N][Kd].
__global__ __launch_bounds__(256)
void prep_kernel(const float* __restrict__ W2, const float* __restrict__ W3,
                 const float* __restrict__ W4, const float* __restrict__ W5,
                 const float* __restrict__ Wu1, const float* __restrict__ Wu2,
                 __half* __restrict__ wh)
{
    __shared__ float tile[32][33];
    int b = blockIdx.x;
    if (b == 0 && threadIdx.x == 0) g_gmax = 0;
    const float* src; __half* dst; int N, CIN, Kdp, gx; bool perm;
    if      (b < 64)   { src=W2;  dst=wh+WOFF_W2; N=64;  CIN=64;  Kdp=1024; gx=32; perm=true; }
    else if (b < 192)  { src=W3;  dst=wh+WOFF_W3; N=128; CIN=64;  Kdp=1024; gx=32; perm=true;  b-=64; }
    else if (b < 448)  { src=W4;  dst=wh+WOFF_W4; N=128; CIN=128; Kdp=2048; gx=64; perm=true;  b-=192; }
    else if (b < 960)  { src=W5;  dst=wh+WOFF_W5; N=256; CIN=128; Kdp=2048; gx=64; perm=true;  b-=448; }
    else if (b < 1008) { src=Wu1; dst=wh+WOFF_U1; N=128; CIN=0;   Kdp=384;  gx=12; perm=false; b-=960; }
    else               { src=Wu2; dst=wh+WOFF_U2; N=32;  CIN=0;   Kdp=192;  gx=6;  perm=false; b-=1008; }
    int kb = (b % gx)*32, nb = (b / gx)*32;
    int tx = threadIdx.x & 31, ty = threadIdx.x >> 5;   // 32 x 8
    if (perm) {
        #pragma unroll
        for (int r = 0; r < 32; r += 8) {
            int i = ty + r;
            int p  = i & 15;                 // (kb+i)&15, since 32|kb
            int cc = (kb >> 4) + (i >> 4);   // channel
            tile[i][tx] = (p < 15) ? src[(size_t)(p*CIN + cc)*N + nb + tx] : 0.f;
        }
        __syncthreads();
        #pragma unroll
        for (int r = 0; r < 32; r += 8)
            dst[(size_t)(nb+ty+r)*Kdp + kb + tx] = __float2half(tile[tx][ty+r]);
    } else {
        #pragma unroll
        for (int r = 0; r < 32; r += 8)
            tile[ty+r][tx] = src[(size_t)(kb+ty+r)*N + nb + tx];
        __syncthreads();
        #pragma unroll
        for (int r = 0; r < 32; r += 8)
            dst[(size_t)(nb+ty+r)*Kdp + kb + tx] = __float2half(tile[tx][ty+r]);
    }
}

// ---------------- layer 1: KPConv Cin=1 Cout=64 ----------------------------------
__global__ __launch_bounds__(256)
void conv1_kernel(const float* __restrict__ pts, const int* __restrict__ neigh,
                  const float* __restrict__ feats, const float* __restrict__ kp,
                  const float* __restrict__ W1, __half* __restrict__ out)
{
    const float extent = 0.5f;
    __shared__ float sdiff[4][K_][3];
    __shared__ float sfeat[4][K_];
    __shared__ float sinfl[4][K_*P_];
    __shared__ float sfk[4][P_];
    int pt = threadIdx.x >> 6;
    int t  = threadIdx.x & 63;
    int n  = blockIdx.x * 4 + pt;
    if (t < K_) {
        int idx = neigh[n*K_+t];
        float qx = pts[n*3+0], qy = pts[n*3+1], qz = pts[n*3+2];
        sdiff[pt][t][0] = pts[idx*3+0]-qx;
        sdiff[pt][t][1] = pts[idx*3+1]-qy;
        sdiff[pt][t][2] = pts[idx*3+2]-qz;
        sfeat[pt][t] = feats[idx];
    }
    __syncthreads();
    for (int i = t; i < K_*P_; i += 64) {
        int k = i / P_, p = i % P_;
        float dx = sdiff[pt][k][0] - kp[p*3+0]*extent;
        float dy = sdiff[pt][k][1] - kp[p*3+1]*extent;
        float dz = sdiff[pt][k][2] - kp[p*3+2]*extent;
        float dist = sqrtf(dx*dx+dy*dy+dz*dz);
        sinfl[pt][i] = fmaxf(0.f, 1.f - dist/extent);
    }
    __syncthreads();
    if (t < P_) {
        float acc = 0.f;
        #pragma unroll
        for (int k = 0; k < K_; k++) acc += sinfl[pt][k*P_+t]*sfeat[pt][k];
        sfk[pt][t] = acc;
    }
    __syncthreads();
    float acc = 0.f;
    #pragma unroll
    for (int p = 0; p < P_; p++) acc += sfk[pt][p]*W1[p*64+t];
    out[n*64+t] = __float2half(acc > 0.f ? acc : 0.1f*acc);
}

// ---------------- helpers ---------------------------------------------------------
__device__ __forceinline__ void ldsm4t(uint32_t& r0, uint32_t& r1, uint32_t& r2,
                                       uint32_t& r3, uint32_t addr)
{
    asm volatile("ldmatrix.sync.aligned.m8n8.x4.trans.shared.b16 {%0,%1,%2,%3}, [%4];"
                 : "=r"(r0), "=r"(r1), "=r"(r2), "=r"(r3) : "r"(addr));
}
__device__ __forceinline__ void cpasync16(uint32_t dst, const void* src, bool valid) {
    int sz = valid ? 16 : 0;
    asm volatile("cp.async.cg.shared.global [%0], [%1], 16, %2;\n"
                 :: "r"(dst), "l"(src), "r"(sz));
}

// ================= fused KPConv: gather-MMA (smem fk) + weight GEMM ===============
// Phase A: 16 warps, each gathers 4 (point, 64-channel-half) tasks via
//          ldmatrix.trans + m16n8k16 MMA; fk tile kept in smem, k = c*16 + p.
// Phase B: C[tile] = leaky(fk_s @ Bt^T), Bt half [BN][KDP], 3-stage cp.async B.
template<int CIN, int BM, int BN>
__global__ __launch_bounds__(512)
void kpconv_fused(const float* __restrict__ qpts, const float* __restrict__ spts,
                  const int* __restrict__ neigh, const __half* __restrict__ feats,
                  const float* __restrict__ kp, float extent,
                  const __half* __restrict__ Bt, __half* __restrict__ Co, int Npts)
{
    constexpr int CH  = CIN / 64;          // channel halves per point
    constexpr int KDP = CIN * 16;          // padded k
    constexpr int SFK = KDP + 8;           // fk_s row stride (halfs)
    constexpr int MW  = BM / 16, NW = 16 / MW;
    constexpr int WNC = BN / NW, NJ = WNC / 8;
    constexpr int NK  = KDP / 32;
    constexpr int NFW = 32 * 72;           // nf staging halfs per warp

    extern __shared__ __align__(16) __half sm[];
    __half* fk_s = sm;                     // BM * SFK
    __half* ovl  = sm + BM * SFK;          // overlay: nf staging | Bs (3 stages)

    const int tid = threadIdx.x, w = tid >> 5, lane = tid & 31;
    const int g = lane >> 2, t4 = lane & 3;
    const int bm = blockIdx.x * BM;

    // ================= Phase A: gather into fk_s =================
    {
        __half* nf = ovl + w * NFW;
        const uint32_t nf_base = (uint32_t)__cvta_generic_to_shared(nf);
        const float inv_e = 1.0f / extent;
        const int grp = lane >> 3, jj = lane & 7;
        #pragma unroll
        for (int tt = 0; tt < 4; tt++) {
            int task  = w * 4 + tt;
            int point = task / CH;
            int choff = (task % CH) * 64;
            int n = bm + point;
            if (n < Npts) {
                int myidx = neigh[n*K_ + lane];
                float qx = qpts[n*3+0], qy = qpts[n*3+1], qz = qpts[n*3+2];
                float mdx = spts[myidx*3+0]-qx;
                float mdy = spts[myidx*3+1]-qy;
                float mdz = spts[myidx*3+2]-qz;
                // stage 32 neighbor rows x 64 channels
                #pragma unroll
                for (int r = 0; r < 8; r++) {
                    int rr = r*4 + (lane>>3);
                    int idx = __shfl_sync(0xffffffffu, myidx, rr);
                    int ch  = (lane&7)*8;
                    uint4 v = *(const uint4*)(feats + (size_t)idx*CIN + choff + ch);
                    *(uint4*)&nf[rr*72 + ch] = v;
                }
                // influence B-fragments via shuffle of per-lane diffs
                uint32_t bfr[2][2][2];
                #pragma unroll
                for (int nt = 0; nt < 2; nt++) {
                    int p = nt*8 + g;
                    bool pv = p < P_;
                    float px = 0.f, py = 0.f, pz = 0.f;
                    if (pv) { px = kp[p*3+0]*extent; py = kp[p*3+1]*extent; pz = kp[p*3+2]*extent; }
                    #pragma unroll
                    for (int ks = 0; ks < 2; ks++) {
                        int kb = ks*16 + 2*t4;
                        float v[4];
                        #pragma unroll
                        for (int j = 0; j < 4; j++) {
                            int k = kb + (j>>1)*8 + (j&1);
                            float dx = __shfl_sync(0xffffffffu, mdx, k) - px;
                            float dy = __shfl_sync(0xffffffffu, mdy, k) - py;
                            float dz = __shfl_sync(0xffffffffu, mdz, k) - pz;
                            float dd = sqrtf(dx*dx+dy*dy+dz*dz);
                            v[j] = pv ? fmaxf(0.f, 1.f - dd*inv_e) : 0.f;
                        }
                        __half2 h0 = __floats2half2_rn(v[0], v[1]);
                        __half2 h1 = __floats2half2_rn(v[2], v[3]);
                        bfr[nt][ks][0] = *reinterpret_cast<uint32_t*>(&h0);
                        bfr[nt][ks][1] = *reinterpret_cast<uint32_t*>(&h1);
                    }
                }
                __syncwarp();
                // MMAs: D[c][p] = nf^T @ infl
                float d[4][2][4];
                #pragma unroll
                for (int mt = 0; mt < 4; mt++)
                    #pragma unroll
                    for (int nt = 0; nt < 2; nt++) {
                        d[mt][nt][0]=0.f; d[mt][nt][1]=0.f; d[mt][nt][2]=0.f; d[mt][nt][3]=0.f;
                    }
                #pragma unroll
                for (int mt = 0; mt < 4; mt++) {
                    #pragma unroll
                    for (int ks = 0; ks < 2; ks++) {
                        int krow = ks*16 + ((grp & 2) ? 8 : 0) + jj;
                        int mcol = mt*16 + ((grp & 1) ? 8 : 0);
                        uint32_t addr = nf_base + (uint32_t)(krow*72 + mcol)*2u;
                        uint32_t a0,a1,a2,a3;
                        ldsm4t(a0,a1,a2,a3, addr);
                        #pragma unroll
                        for (int nt = 0; nt < 2; nt++)
                            asm volatile(
                                "mma.sync.aligned.m16n8k16.row.col.f32.f16.f16.f32 "
                                "{%0,%1,%2,%3},{%4,%5,%6,%7},{%8,%9},{%0,%1,%2,%3};\n"
                                : "+f"(d[mt][nt][0]), "+f"(d[mt][nt][1]),
                                  "+f"(d[mt][nt][2]), "+f"(d[mt][nt][3])
                                : "r"(a0), "r"(a1), "r"(a2), "r"(a3),
                                  "r"(bfr[nt][ks][0]), "r"(bfr[nt][ks][1]));
                    }
                }
                // D -> fk_s as half2 at k = (choff+c)*16 + p0 (pairs p0,p0+1)
                __half* frow = fk_s + (size_t)point * SFK;
                #pragma unroll
                for (int mt = 0; mt < 4; mt++) {
                    int c0 = choff + mt*16 + g;
                    #pragma unroll
                    for (int nt = 0; nt < 2; nt++) {
                        int p0 = nt*8 + 2*t4;
                        *(__half2*)&frow[c0*16 + p0]     = __floats2half2_rn(d[mt][nt][0], d[mt][nt][1]);
                        *(__half2*)&frow[(c0+8)*16 + p0] = __floats2half2_rn(d[mt][nt][2], d[mt][nt][3]);
                    }
                }
            }
            __syncwarp();
        }
    }
    __syncthreads();

    // ================= Phase B: fk_s @ W =================
    const int wm = w / NW, wn = w % NW;
    float acc[NJ][4];
    #pragma unroll
    for (int j = 0; j < NJ; j++) { acc[j][0]=0.f; acc[j][1]=0.f; acc[j][2]=0.f; acc[j][3]=0.f; }

    auto issueB = [&](int s, int k0) {
        __half* Bst = ovl + s * (BN*40);
        for (int ci = tid; ci < BN*4; ci += 512) {
            int row = ci >> 2, koff = (ci & 3) * 8;
            cpasync16((uint32_t)__cvta_generic_to_shared(&Bst[row*40 + koff]),
                      Bt + (size_t)row*KDP + k0 + koff, true);
        }
        asm volatile("cp.async.commit_group;\n");
    };

    issueB(0, 0);
    issueB(1, 32);
    int st = 0;
    for (int kt = 0; kt < NK; kt++) {
        asm volatile("cp.async.wait_group 1;\n");
        __syncthreads();
        {
            const __half* Bst = ovl + st * (BN*40);
            const __half* Arow = fk_s + (size_t)(wm*16 + g)*SFK + kt*32 + 2*t4;
            #pragma unroll
            for (int k0 = 0; k0 < 32; k0 += 16) {
                uint32_t a0 = *(const uint32_t*)(Arow + k0);
                uint32_t a1 = *(const uint32_t*)(Arow + k0 + 8*SFK);
                uint32_t a2 = *(const uint32_t*)(Arow + k0 + 8);
                uint32_t a3 = *(const uint32_t*)(Arow + k0 + 8*SFK + 8);
                #pragma unroll
                for (int j = 0; j < NJ; j++) {
                    int col = wn*WNC + j*8 + g;
                    uint32_t b0 = *(const uint32_t*)&Bst[col*40 + k0 + 2*t4];
                    uint32_t b1 = *(const uint32_t*)&Bst[col*40 + k0 + 2*t4 + 8];
                    asm volatile(
                        "mma.sync.aligned.m16n8k16.row.col.f32.f16.f16.f32 "
                        "{%0,%1,%2,%3},{%4,%5,%6,%7},{%8,%9},{%0,%1,%2,%3};\n"
                        : "+f"(acc[j][0]), "+f"(acc[j][1]), "+f"(acc[j][2]), "+f"(acc[j][3])
                        : "r"(a0), "r"(a1), "r"(a2), "r"(a3), "r"(b0), "r"(b1));
                }
            }
        }
        int nx = kt + 2;
        int ws = st + 2; if (ws >= 3) ws -= 3;
        if (nx < NK) issueB(ws, nx << 5);
        else asm volatile("cp.async.commit_group;\n");
        if (++st == 3) st = 0;
    }

    // epilogue: leaky relu, half2 stores
    int r0 = bm + wm*16 + g;
    #pragma unroll
    for (int j = 0; j < NJ; j++) {
        int col = wn*WNC + j*8 + 2*t4;
        float v0 = acc[j][0], v1 = acc[j][1], v2 = acc[j][2], v3 = acc[j][3];
        v0 = v0 > 0.f ? v0 : 0.1f*v0;  v1 = v1 > 0.f ? v1 : 0.1f*v1;
        v2 = v2 > 0.f ? v2 : 0.1f*v2;  v3 = v3 > 0.f ? v3 : 0.1f*v3;
        if (r0 < Npts)     *(__half2*)&Co[(size_t)r0*BN + col]     = __floats2half2_rn(v0, v1);
        if (r0 + 8 < Npts) *(__half2*)&Co[(size_t)(r0+8)*BN + col] = __floats2half2_rn(v2, v3);
    }
}

// ================= fp16 tensor-core GEMM (decoder): 3-stage cp.async ==============
template<int MF, int NF, bool LEAKY, bool CAT, bool OUTHALF, bool STATS>
__global__ __launch_bounds__(256)
void gemm_tc(const __half* __restrict__ A, const __half* __restrict__ Bt,
             void* __restrict__ Cv, int M, int N, int Kd,
             const int* __restrict__ upidx, const __half* __restrict__ Askip,
             int c_up, int c_skip, float* __restrict__ rowsum, int* __restrict__ gmaxp)
{
    constexpr int BM = MF * 64, BN = NF * 64;
    extern __shared__ __align__(16) __half dynsm[];
    __half (*As)[BM][40] = reinterpret_cast<__half (*)[BM][40]>(dynsm);
    __half (*Bs)[BN][40] = reinterpret_cast<__half (*)[BN][40]>(dynsm + 3*BM*40);
    __shared__ float swm[8];

    const int bm = blockIdx.y * BM, bn = blockIdx.x * BN;
    const int tid  = threadIdx.x;
    const int warp = tid >> 5, lane = tid & 31;
    const int wm = warp >> 1, wn = warp & 1;
    const int g  = lane >> 2, tg = lane & 3;

    float c[MF][4*NF][4];
    #pragma unroll
    for (int i = 0; i < MF; i++)
        #pragma unroll
        for (int j = 0; j < 4*NF; j++) {
            c[i][j][0]=0.f; c[i][j][1]=0.f; c[i][j][2]=0.f; c[i][j][3]=0.f;
        }

    const int ar = tid >> 2;
    const int ac = (tid & 3) * 8;

    int ridx[MF];
    if (CAT) {
        #pragma unroll
        for (int i = 0; i < MF; i++) {
            int r = bm + ar + i * 64;
            ridx[i] = (r < M) ? upidx[r] : 0;
        }
    }

    const int nk = Kd >> 5;

    auto issue = [&](int s, int k0) {
        #pragma unroll
        for (int i = 0; i < MF; i++) {
            int r = ar + i * 64;
            bool v = (bm + r) < M;
            const __half* src;
            if (CAT) {
                int kc = k0 + ac;
                src = (kc < c_up) ? (A + (size_t)ridx[i] * c_up + kc)
                                  : (Askip + (size_t)(bm + r) * c_skip + (kc - c_up));
                if (!v) src = A;
            } else {
                src = v ? (A + (size_t)(bm + r) * Kd + k0 + ac) : A;
            }
            cpasync16((uint32_t)__cvta_generic_to_shared(&As[s][r][ac]), src, v);
        }
        #pragma unroll
        for (int j = 0; j < NF; j++) {
            int nrow = ar + j * 64;
            bool v = (bn + nrow) < N;
            const __half* srcb = v ? (Bt + (size_t)(bn + nrow) * Kd + k0 + ac) : Bt;
            cpasync16((uint32_t)__cvta_generic_to_shared(&Bs[s][nrow][ac]), srcb, v);
        }
        asm volatile("cp.async.commit_group;\n");
    };

    auto compute = [&](int s) {
        #pragma unroll
        for (int k0 = 0; k0 < 32; k0 += 16) {
            uint32_t a[MF][4], bf[4*NF][2];
            #pragma unroll
            for (int i = 0; i < MF; i++) {
                int r = wm * MF * 16 + i * 16 + g;
                a[i][0] = *(const uint32_t*)&As[s][r    ][k0 + 2*tg    ];
                a[i][1] = *(const uint32_t*)&As[s][r + 8][k0 + 2*tg    ];
                a[i][2] = *(const uint32_t*)&As[s][r    ][k0 + 2*tg + 8];
                a[i][3] = *(const uint32_t*)&As[s][r + 8][k0 + 2*tg + 8];
            }
            #pragma unroll
            for (int j = 0; j < 4*NF; j++) {
                int col = wn * NF * 32 + j * 8 + g;
                bf[j][0] = *(const uint32_t*)&Bs[s][col][k0 + 2*tg    ];
                bf[j][1] = *(const uint32_t*)&Bs[s][col][k0 + 2*tg + 8];
            }
            #pragma unroll
            for (int i = 0; i < MF; i++)
                #pragma unroll
                for (int j = 0; j < 4*NF; j++)
                    asm volatile(
                        "mma.sync.aligned.m16n8k16.row.col.f32.f16.f16.f32 "
                        "{%0,%1,%2,%3},{%4,%5,%6,%7},{%8,%9},{%0,%1,%2,%3};\n"
                        : "+f"(c[i][j][0]), "+f"(c[i][j][1]),
                          "+f"(c[i][j][2]), "+f"(c[i][j][3])
                        : "r"(a[i][0]), "r"(a[i][1]), "r"(a[i][2]), "r"(a[i][3]),
                          "r"(bf[j][0]), "r"(bf[j][1]));
        }
    };

    issue(0, 0);
    issue(1, 32);
    int st = 0;
    for (int kt = 0; kt < nk; kt++) {
        asm volatile("cp.async.wait_group 1;\n");
        __syncthreads();
        compute(st);
        int nx = kt + 2;
        int ws = st + 2; if (ws >= 3) ws -= 3;
        if (nx < nk) issue(ws, nx << 5);
        else asm volatile("cp.async.commit_group;\n");
        if (++st == 3) st = 0;
    }

    __half* Ch = (__half*)Cv;
    float*  Cf = (float*)Cv;
    #pragma unroll
    for (int i = 0; i < MF; i++) {
        int r0 = bm + wm * MF * 16 + i * 16 + g;
        #pragma unroll
        for (int j = 0; j < 4*NF; j++) {
            int col = bn + wn * NF * 32 + j * 8 + 2 * tg;
            if (col < N) {
                if (r0 < M) {
                    float v0 = c[i][j][0], v1 = c[i][j][1];
                    if (LEAKY) { v0 = v0 > 0.f ? v0 : 0.1f*v0; v1 = v1 > 0.f ? v1 : 0.1f*v1; }
                    if (OUTHALF) *(__half2*)&Ch[(size_t)r0 * N + col] = __floats2half2_rn(v0, v1);
                    else { Cf[(size_t)r0 * N + col] = v0; Cf[(size_t)r0 * N + col + 1] = v1; }
                }
                if (r0 + 8 < M) {
                    float v2 = c[i][j][2], v3 = c[i][j][3];
                    if (LEAKY) { v2 = v2 > 0.f ? v2 : 0.1f*v2; v3 = v3 > 0.f ? v3 : 0.1f*v3; }
                    if (OUTHALF) *(__half2*)&Ch[(size_t)(r0+8) * N + col] = __floats2half2_rn(v2, v3);
                    else { Cf[(size_t)(r0+8) * N + col] = v2; Cf[(size_t)(r0+8) * N + col + 1] = v3; }
                }
            }
        }
    }

    if (STATS) {
        float wmax = 0.f;
        if (wn == 0) {
            #pragma unroll
            for (int i = 0; i < MF; i++) {
                float sl = 0.f, sh = 0.f, ml = 0.f, mh = 0.f;
                #pragma unroll
                for (int j = 0; j < 4*NF; j++) {
                    sl += c[i][j][0] + c[i][j][1];
                    sh += c[i][j][2] + c[i][j][3];
                    ml = fmaxf(ml, fmaxf(c[i][j][0], c[i][j][1]));
                    mh = fmaxf(mh, fmaxf(c[i][j][2], c[i][j][3]));
                }
                sl += __shfl_xor_sync(0xffffffffu, sl, 1);
                sl += __shfl_xor_sync(0xffffffffu, sl, 2);
                sh += __shfl_xor_sync(0xffffffffu, sh, 1);
                sh += __shfl_xor_sync(0xffffffffu, sh, 2);
                ml = fmaxf(ml, __shfl_xor_sync(0xffffffffu, ml, 1));
                ml = fmaxf(ml, __shfl_xor_sync(0xffffffffu, ml, 2));
                mh = fmaxf(mh, __shfl_xor_sync(0xffffffffu, mh, 1));
                mh = fmaxf(mh, __shfl_xor_sync(0xffffffffu, mh, 2));
                int r0 = bm + wm * MF * 16 + i * 16 + g;
                if (tg == 0) {
                    if (r0 < M)     rowsum[r0]     = sl;
                    if (r0 + 8 < M) rowsum[r0 + 8] = sh;
                }
                wmax = fmaxf(wmax, fmaxf(ml, mh));
            }
        }
        #pragma unroll
        for (int o = 16; o; o >>= 1)
            wmax = fmaxf(wmax, __shfl_xor_sync(0xffffffffu, wmax, o));
        if (lane == 0) swm[warp] = wmax;
        __syncthreads();
        if (tid == 0) {
            float bmv = swm[0];
            #pragma unroll
            for (int ww = 1; ww < 8; ww++) bmv = fmaxf(bmv, swm[ww]);
            atomicMax(gmaxp, __float_as_int(fmaxf(bmv, 0.f)));
        }
    }
}

// ---------------- detection head: float4 neighbor accumulation -------------------
__global__ void scores_kernel(const int* __restrict__ neigh, const float* __restrict__ ff,
                              const float* __restrict__ rowsum,
                              float* __restrict__ out_fnorm, float* __restrict__ out_scores)
{
    int warp = (blockIdx.x*blockDim.x + threadIdx.x) >> 5;
    int lane = threadIdx.x & 31;
    if (warp >= N0_) return;
    float fraw = ff[(size_t)warp*32 + lane];
    float s2 = fraw*fraw;
    #pragma unroll
    for (int o = 16; o; o >>= 1) s2 += __shfl_xor_sync(0xffffffffu, s2, o);
    float nrm = fmaxf(sqrtf(s2), 1e-12f);
    out_fnorm[(size_t)warp*32 + lane] = fraw / nrm;

    float inv = 1.0f / (__int_as_float(g_gmax) + 1e-6f);
    int myidx = neigh[(size_t)warp*32 + lane];

    int nz = (rowsum[myidx] != 0.f) ? 1 : 0;
    #pragma unroll
    for (int o = 16; o; o >>= 1) nz += __shfl_xor_sync(0xffffffffu, nz, o);
    float nnumf = (float)(nz < 1 ? 1 : nz);

    const int c4 = lane & 7, kg = lane >> 3;
    float4 sum4 = make_float4(0.f,0.f,0.f,0.f);
    float4 max4 = make_float4(-1e30f,-1e30f,-1e30f,-1e30f);
    #pragma unroll
    for (int i = 0; i < 8; i++) {
        int idx = __shfl_sync(0xffffffffu, myidx, i*4 + kg);
        float4 v = *(const float4*)(ff + (size_t)idx*32 + c4*4);
        sum4.x += v.x; sum4.y += v.y; sum4.z += v.z; sum4.w += v.w;
        max4.x = fmaxf(max4.x, v.x); max4.y = fmaxf(max4.y, v.y);
        max4.z = fmaxf(max4.z, v.z); max4.w = fmaxf(max4.w, v.w);
    }
    #pragma unroll
    for (int o = 8; o <= 16; o <<= 1) {
        sum4.x += __shfl_xor_sync(0xffffffffu, sum4.x, o);
        sum4.y += __shfl_xor_sync(0xffffffffu, sum4.y, o);
        sum4.z += __shfl_xor_sync(0xffffffffu, sum4.z, o);
        sum4.w += __shfl_xor_sync(0xffffffffu, sum4.w, o);
        max4.x = fmaxf(max4.x, __shfl_xor_sync(0xffffffffu, max4.x, o));
        max4.y = fmaxf(max4.y, __shfl_xor_sync(0xffffffffu, max4.y, o));
        max4.z = fmaxf(max4.z, __shfl_xor_sync(0xffffffffu, max4.z, o));
        max4.w = fmaxf(max4.w, __shfl_xor_sync(0xffffffffu, max4.w, o));
    }
    int src = lane >> 2;
    float sx = __shfl_sync(0xffffffffu, sum4.x, src);
    float sy = __shfl_sync(0xffffffffu, sum4.y, src);
    float sz = __shfl_sync(0xffffffffu, sum4.z, src);
    float sw = __shfl_sync(0xffffffffu, sum4.w, src);
    float mx = __shfl_sync(0xffffffffu, max4.x, src);
    float my = __shfl_sync(0xffffffffu, max4.y, src);
    float mz = __shfl_sync(0xffffffffu, max4.z, src);
    float mw = __shfl_sync(0xffffffffu, max4.w, src);
    int comp = lane & 3;
    float msum = (comp == 0) ? sx : (comp == 1) ? sy : (comp == 2) ? sz : sw;
    float mraw = (comp == 0) ? mx : (comp == 1) ? my : (comp == 2) ? mz : mw;

    float f = fraw * inv;
    float mean = msum * inv / nnumf;
    float nmax = mraw * inv;
    float x = f - mean;
    float lms = fmaxf(x, 0.f) + log1pf(expf(-fabsf(x)));
    float dmax = f;
    #pragma unroll
    for (int o = 16; o; o >>= 1) dmax = fmaxf(dmax, __shfl_xor_sync(0xffffffffu, dmax, o));
    float sc = lms * f / (1e-6f + dmax);
    float det = (f == nmax) ? 1.f : 0.f;
    #pragma unroll
    for (int o = 16; o; o >>= 1) {
        sc  = fmaxf(sc,  __shfl_xor_sync(0xffffffffu, sc, o));
        det = fmaxf(det, __shfl_xor_sync(0xffffffffu, det, o));
    }
    if (lane == 0) out_scores[warp] = sc * det;
}

// ---------------- launch ----------------------------------------------------------
extern "C" void kernel_launch(void* const* d_in, const int* in_sizes, int n_in,
                              void* d_out, int out_size)
{
    const float* features   = (const float*)d_in[0];
    const float* points0    = (const float*)d_in[1];
    const float* points1    = (const float*)d_in[2];
    const float* points2    = (const float*)d_in[3];
    const int*   neighbors0 = (const int*)d_in[4];
    const int*   neighbors1 = (const int*)d_in[5];
    const int*   neighbors2 = (const int*)d_in[6];
    const int*   pools0     = (const int*)d_in[7];
    const int*   pools1     = (const int*)d_in[8];
    const int*   upsamples0 = (const int*)d_in[9];
    const int*   upsamples1 = (const int*)d_in[10];
    const float* kpoints    = (const float*)d_in[11];
    const float* W1  = (const float*)d_in[12];
    const float* W2  = (const float*)d_in[13];
    const float* W3  = (const float*)d_in[14];
    const float* W4  = (const float*)d_in[15];
    const float* W5  = (const float*)d_in[16];
    const float* Wu1 = (const float*)d_in[17];
    const float* Wu2 = (const float*)d_in[18];
    float* out = (float*)d_out;

    __half *f1,*f2,*f3,*f4,*f5,*fu1,*wh;
    float *ff,*rowsum;
    int *gmaxp;
    cudaGetSymbolAddress((void**)&f1,  g_f1);
    cudaGetSymbolAddress((void**)&f2,  g_f2);
    cudaGetSymbolAddress((void**)&f3,  g_f3);
    cudaGetSymbolAddress((void**)&f4,  g_f4);
    cudaGetSymbolAddress((void**)&f5,  g_f5);
    cudaGetSymbolAddress((void**)&fu1, g_fu1);
    cudaGetSymbolAddress((void**)&wh,  g_wh);
    cudaGetSymbolAddress((void**)&ff,  g_ff);
    cudaGetSymbolAddress((void**)&rowsum, g_rowsum);
    cudaGetSymbolAddress((void**)&gmaxp,  g_gmax);

    // fused kernel smem: fk tile + overlay(36864 halfs)
    const int smA = (64*(64*16+8)  + 36864) * 2;   // CIN=64  : 205,824 B
    const int smB = (32*(128*16+8) + 36864) * 2;   // CIN=128 : 205,312 B
    cudaFuncSetAttribute(kpconv_fused<64,64,64>,   cudaFuncAttributeMaxDynamicSharedMemorySize, smA);
    cudaFuncSetAttribute(kpconv_fused<64,64,128>,  cudaFuncAttributeMaxDynamicSharedMemorySize, smA);
    cudaFuncSetAttribute(kpconv_fused<128,32,128>, cudaFuncAttributeMaxDynamicSharedMemorySize, smB);
    cudaFuncSetAttribute(kpconv_fused<128,32,256>, cudaFuncAttributeMaxDynamicSharedMemorySize, smB);

    const int sm21 = 3*(128+ 64)*40*2;
    const int sm22 = 3*(128+128)*40*2;
    cudaFuncSetAttribute(gemm_tc<2,2,true,true,true,false>,  cudaFuncAttributeMaxDynamicSharedMemorySize, sm22);
    cudaFuncSetAttribute(gemm_tc<2,1,false,true,false,true>, cudaFuncAttributeMaxDynamicSharedMemorySize, sm21);

    // ---- prep (all weight transposes + gmax reset, one launch) ----
    prep_kernel<<<1014, 256>>>(W2, W3, W4, W5, Wu1, Wu2, wh);

    // ---- encoder ----
    conv1_kernel<<<N0_/4, 256>>>(points0, neighbors0, features, kpoints, W1, f1);

    kpconv_fused<64,64,64><<<(N1_+63)/64, 512, smA>>>(points1, points0, pools0, f1,
                                                      kpoints, 0.5f, wh+WOFF_W2, f2, N1_);
    kpconv_fused<64,64,128><<<(N1_+63)/64, 512, smA>>>(points1, points1, neighbors1, f2,
                                                       kpoints, 1.0f, wh+WOFF_W3, f3, N1_);
    kpconv_fused<128,32,128><<<(N2_+31)/32, 512, smB>>>(points2, points1, pools1, f3,
                                                        kpoints, 1.0f, wh+WOFF_W4, f4, N2_);
    kpconv_fused<128,32,256><<<(N2_+31)/32, 512, smB>>>(points2, points2, neighbors2, f4,
                                                        kpoints, 2.0f, wh+WOFF_W5, f5, N2_);

    // ---- decoder (concat fused into GEMM A-load) ----
    gemm_tc<2,2,true,true,true,false><<<dim3(1,(N1_+127)/128), 256, sm22>>>(f5, wh+WOFF_U1, fu1, N1_, 128, 384,
                                                                            upsamples1, f3, 256, 128, nullptr, nullptr);
    gemm_tc<2,1,false,true,false,true><<<dim3(1,(N0_+127)/128), 256, sm21>>>(fu1, wh+WOFF_U2, ff, N0_, 32, 192,
                                                                             upsamples0, f1, 128, 64, rowsum, gmaxp);

    // ---- detection head + outputs ----
    scores_kernel<<<(N0_ + 7)/8, 256>>>(neighbors0, ff, rowsum, out, out + (size_t)N0_*32);
}

// round 9
// speedup vs baseline: 1.0495x; 1.0495x over previous
#include <cuda_runtime.h>
#include <cuda_fp16.h>
#include <math.h>
#include <stdint.h>

#define N0_ 60000
#define N1_ 15000
#define N2_ 3750
#define K_  32
#define P_  15

// ---------------- intermediate buffers (device globals; no allocations) ----------
__device__ __align__(16) __half g_f1 [N0_*64];        // skip0
__device__ __align__(16) __half g_f2 [N1_*64];
__device__ __align__(16) __half g_f3 [N1_*128];       // skip1
__device__ __align__(16) __half g_f4 [N2_*128];
__device__ __align__(16) __half g_f5 [N2_*256];
__device__ __align__(16) __half g_fk [N1_*P_*64];     // reused by all gathers
__device__ __align__(16) __half g_fu1[N1_*128];
__device__ __align__(16) float  g_ff [N0_*32];
__device__ __align__(16) __half g_wh [976896];        // all transposed half weights
__device__ float g_rowsum[N0_];
__device__ int g_gmax;

#define WOFF_W2  0
#define WOFF_W3  61440
#define WOFF_W4  184320
#define WOFF_W5  430080
#define WOFF_U1  921600
#define WOFF_U2  970752

// ---------------- fused prep: all 6 weight transposes fp32[Kd][N]->half[N][Kd] ----
__global__ __launch_bounds__(256)
void prep_kernel(const float* __restrict__ W2, const float* __restrict__ W3,
                 const float* __restrict__ W4, const float* __restrict__ W5,
                 const float* __restrict__ Wu1, const float* __restrict__ Wu2,
                 __half* __restrict__ wh)
{
    __shared__ float tile[32][33];
    int b = blockIdx.x;
    if (b == 0 && threadIdx.x == 0) g_gmax = 0;
    const float* src; __half* dst; int Kd, N, gx;
    if      (b < 60)  { src=W2;  dst=wh+WOFF_W2; Kd=960;  N=64;  gx=30; }
    else if (b < 180) { src=W3;  dst=wh+WOFF_W3; Kd=960;  N=128; gx=30; b-=60; }
    else if (b < 420) { src=W4;  dst=wh+WOFF_W4; Kd=1920; N=128; gx=60; b-=180; }
    else if (b < 900) { src=W5;  dst=wh+WOFF_W5; Kd=1920; N=256; gx=60; b-=420; }
    else if (b < 948) { src=Wu1; dst=wh+WOFF_U1; Kd=384;  N=128; gx=12; b-=900; }
    else              { src=Wu2; dst=wh+WOFF_U2; Kd=192;  N=32;  gx=6;  b-=948; }
    int kb = (b % gx)*32, nb = (b / gx)*32;
    int tx = threadIdx.x & 31, ty = threadIdx.x >> 5;   // 32 x 8
    #pragma unroll
    for (int r = 0; r < 32; r += 8)
        tile[ty+r][tx] = src[(size_t)(kb+ty+r)*N + nb + tx];
    __syncthreads();
    #pragma unroll
    for (int r = 0; r < 32; r += 8)
        dst[(size_t)(nb+ty+r)*Kd + kb + tx] = __float2half(tile[tx][ty+r]);
}

// ---------------- layer 1: KPConv Cin=1 Cout=64 ----------------------------------
__global__ __launch_bounds__(256)
void conv1_kernel(const float* __restrict__ pts, const int* __restrict__ neigh,
                  const float* __restrict__ feats, const float* __restrict__ kp,
                  const float* __restrict__ W1, __half* __restrict__ out)
{
    const float extent = 0.5f;
    __shared__ float sdiff[4][K_][3];
    __shared__ float sfeat[4][K_];
    __shared__ float sinfl[4][K_*P_];
    __shared__ float sfk[4][P_];
    int pt = threadIdx.x >> 6;
    int t  = threadIdx.x & 63;
    int n  = blockIdx.x * 4 + pt;
    if (t < K_) {
        int idx = neigh[n*K_+t];
        float qx = pts[n*3+0], qy = pts[n*3+1], qz = pts[n*3+2];
        sdiff[pt][t][0] = pts[idx*3+0]-qx;
        sdiff[pt][t][1] = pts[idx*3+1]-qy;
        sdiff[pt][t][2] = pts[idx*3+2]-qz;
        sfeat[pt][t] = feats[idx];
    }
    __syncthreads();
    for (int i = t; i < K_*P_; i += 64) {
        int k = i / P_, p = i % P_;
        float dx = sdiff[pt][k][0] - kp[p*3+0]*extent;
        float dy = sdiff[pt][k][1] - kp[p*3+1]*extent;
        float dz = sdiff[pt][k][2] - kp[p*3+2]*extent;
        float dist = sqrtf(dx*dx+dy*dy+dz*dz);
        sinfl[pt][i] = fmaxf(0.f, 1.f - dist/extent);
    }
    __syncthreads();
    if (t < P_) {
        float acc = 0.f;
        #pragma unroll
        for (int k = 0; k < K_; k++) acc += sinfl[pt][k*P_+t]*sfeat[pt][k];
        sfk[pt][t] = acc;
    }
    __syncthreads();
    float acc = 0.f;
    #pragma unroll
    for (int p = 0; p < P_; p++) acc += sfk[pt][p]*W1[p*64+t];
    out[n*64+t] = __float2half(acc > 0.f ? acc : 0.1f*acc);
}

// ---------------- tensor-core gather (verified R6/R7) -----------------------------
__device__ __forceinline__ void ldsm4t(uint32_t& r0, uint32_t& r1, uint32_t& r2,
                                       uint32_t& r3, uint32_t addr)
{
    asm volatile("ldmatrix.sync.aligned.m8n8.x4.trans.shared.b16 {%0,%1,%2,%3}, [%4];"
                 : "=r"(r0), "=r"(r1), "=r"(r2), "=r"(r3) : "r"(addr));
}

template<int CIN, int WPB>
__global__ __launch_bounds__(32*WPB)
void gather_mma_kernel(const float* __restrict__ qpts, const float* __restrict__ spts,
                       const int* __restrict__ neigh, const __half* __restrict__ feats,
                       const float* __restrict__ kp, float extent,
                       __half* __restrict__ fk, int Npts)
{
    constexpr int STR = CIN + 8;
    constexpr int MT  = CIN / 16;
    __shared__ __half nf[WPB][32][STR];
    __shared__ float  sdiff[WPB][32][4];
    __shared__ int    sidx[WPB][32];

    const int w    = threadIdx.x >> 5;
    const int lane = threadIdx.x & 31;
    const int n    = blockIdx.x * WPB + w;
    if (n >= Npts) return;
    const int g = lane >> 2, t4 = lane & 3;

    {
        int idx = neigh[n*K_ + lane];
        sidx[w][lane] = idx;
        float qx = qpts[n*3+0], qy = qpts[n*3+1], qz = qpts[n*3+2];
        sdiff[w][lane][0] = spts[idx*3+0]-qx;
        sdiff[w][lane][1] = spts[idx*3+1]-qy;
        sdiff[w][lane][2] = spts[idx*3+2]-qz;
    }
    __syncwarp();

    if (CIN == 64) {
        #pragma unroll
        for (int r = 0; r < 8; r++) {
            int row = r*4 + (lane>>3);
            int ch  = (lane&7)*8;
            uint4 v = *(const uint4*)(feats + (size_t)sidx[w][row]*CIN + ch);
            *(uint4*)&nf[w][row][ch] = v;
        }
    } else {
        #pragma unroll
        for (int r = 0; r < 16; r++) {
            int row = r*2 + (lane>>4);
            int ch  = (lane&15)*8;
            uint4 v = *(const uint4*)(feats + (size_t)sidx[w][row]*CIN + ch);
            *(uint4*)&nf[w][row][ch] = v;
        }
    }

    const float inv_e = 1.0f / extent;
    uint32_t bfr[2][2][2];
    #pragma unroll
    for (int nt = 0; nt < 2; nt++) {
        int p = nt*8 + g;
        bool pv = p < P_;
        float px = 0.f, py = 0.f, pz = 0.f;
        if (pv) {
            px = kp[p*3+0]*extent; py = kp[p*3+1]*extent; pz = kp[p*3+2]*extent;
        }
        #pragma unroll
        for (int ks = 0; ks < 2; ks++) {
            int kb = ks*16 + 2*t4;
            float v[4];
            #pragma unroll
            for (int j = 0; j < 4; j++) {
                int k = kb + (j>>1)*8 + (j&1);
                float dx = sdiff[w][k][0]-px;
                float dy = sdiff[w][k][1]-py;
                float dz = sdiff[w][k][2]-pz;
                float d = sqrtf(dx*dx+dy*dy+dz*dz);
                v[j] = pv ? fmaxf(0.f, 1.f - d*inv_e) : 0.f;
            }
            __half2 h0 = __floats2half2_rn(v[0], v[1]);
            __half2 h1 = __floats2half2_rn(v[2], v[3]);
            bfr[nt][ks][0] = *reinterpret_cast<uint32_t*>(&h0);
            bfr[nt][ks][1] = *reinterpret_cast<uint32_t*>(&h1);
        }
    }
    __syncwarp();

    float d[MT][2][4];
    #pragma unroll
    for (int mt = 0; mt < MT; mt++)
        #pragma unroll
        for (int nt = 0; nt < 2; nt++) {
            d[mt][nt][0]=0.f; d[mt][nt][1]=0.f; d[mt][nt][2]=0.f; d[mt][nt][3]=0.f;
        }
    uint32_t nf_base = (uint32_t)__cvta_generic_to_shared(&nf[w][0][0]);
    const int grp = lane >> 3, jj = lane & 7;
    #pragma unroll
    for (int mt = 0; mt < MT; mt++) {
        #pragma unroll
        for (int ks = 0; ks < 2; ks++) {
            int krow = ks*16 + ((grp & 2) ? 8 : 0) + jj;
            int mcol = mt*16 + ((grp & 1) ? 8 : 0);
            uint32_t addr = nf_base + (uint32_t)(krow*STR + mcol)*2u;
            uint32_t a0,a1,a2,a3;
            ldsm4t(a0,a1,a2,a3, addr);
            #pragma unroll
            for (int nt = 0; nt < 2; nt++)
                asm volatile(
                    "mma.sync.aligned.m16n8k16.row.col.f32.f16.f16.f32 "
                    "{%0,%1,%2,%3},{%4,%5,%6,%7},{%8,%9},{%0,%1,%2,%3};\n"
                    : "+f"(d[mt][nt][0]), "+f"(d[mt][nt][1]),
                      "+f"(d[mt][nt][2]), "+f"(d[mt][nt][3])
                    : "r"(a0), "r"(a1), "r"(a2), "r"(a3),
                      "r"(bfr[nt][ks][0]), "r"(bfr[nt][ks][1]));
        }
    }
    __syncwarp();

    #pragma unroll
    for (int mt = 0; mt < MT; mt++) {
        int c = mt*16 + g;
        #pragma unroll
        for (int nt = 0; nt < 2; nt++) {
            int p0 = nt*8 + 2*t4;
            nf[w][p0  ][c  ] = __float2half(d[mt][nt][0]);
            nf[w][p0+1][c  ] = __float2half(d[mt][nt][1]);
            nf[w][p0  ][c+8] = __float2half(d[mt][nt][2]);
            nf[w][p0+1][c+8] = __float2half(d[mt][nt][3]);
        }
    }
    __syncwarp();
    constexpr int CH = P_ * CIN / 8;
    #pragma unroll
    for (int cid = lane; cid < CH; cid += 32) {
        int p = cid / (CIN/8), cc = cid % (CIN/8);
        uint4 v = *(const uint4*)&nf[w][p][cc*8];
        *(uint4*)(fk + (size_t)n*(P_*CIN) + cid*8) = v;
    }
}

// ================= fp16 tensor-core GEMM: 3-stage cp.async, 1 sync/iter ==========
__device__ __forceinline__ void cpasync16(uint32_t dst, const void* src, bool valid) {
    int sz = valid ? 16 : 0;
    asm volatile("cp.async.cg.shared.global [%0], [%1], 16, %2;\n"
                 :: "r"(dst), "l"(src), "r"(sz));
}

template<int MF, int NF, bool LEAKY, bool CAT, bool OUTHALF, bool STATS>
__global__ __launch_bounds__(256)
void gemm_tc(const __half* __restrict__ A, const __half* __restrict__ Bt,
             void* __restrict__ Cv, int M, int N, int Kd,
             const int* __restrict__ upidx, const __half* __restrict__ Askip,
             int c_up, int c_skip, float* __restrict__ rowsum, int* __restrict__ gmaxp)
{
    constexpr int BM = MF * 64, BN = NF * 64;
    extern __shared__ __align__(16) __half dynsm[];
    __half (*As)[BM][40] = reinterpret_cast<__half (*)[BM][40]>(dynsm);
    __half (*Bs)[BN][40] = reinterpret_cast<__half (*)[BN][40]>(dynsm + 3*BM*40);
    __shared__ float swm[8];

    const int bm = blockIdx.y * BM, bn = blockIdx.x * BN;
    const int tid  = threadIdx.x;
    const int warp = tid >> 5, lane = tid & 31;
    const int wm = warp >> 1, wn = warp & 1;
    const int g  = lane >> 2, tg = lane & 3;

    float c[MF][4*NF][4];
    #pragma unroll
    for (int i = 0; i < MF; i++)
        #pragma unroll
        for (int j = 0; j < 4*NF; j++) {
            c[i][j][0]=0.f; c[i][j][1]=0.f; c[i][j][2]=0.f; c[i][j][3]=0.f;
        }

    const int ar = tid >> 2;
    const int ac = (tid & 3) * 8;

    int ridx[MF];
    if (CAT) {
        #pragma unroll
        for (int i = 0; i < MF; i++) {
            int r = bm + ar + i * 64;
            ridx[i] = (r < M) ? upidx[r] : 0;
        }
    }

    const int nk = Kd >> 5;

    auto issue = [&](int s, int k0) {
        #pragma unroll
        for (int i = 0; i < MF; i++) {
            int r = ar + i * 64;
            bool v = (bm + r) < M;
            const __half* src;
            if (CAT) {
                int kc = k0 + ac;
                src = (kc < c_up) ? (A + (size_t)ridx[i] * c_up + kc)
                                  : (Askip + (size_t)(bm + r) * c_skip + (kc - c_up));
                if (!v) src = A;
            } else {
                src = v ? (A + (size_t)(bm + r) * Kd + k0 + ac) : A;
            }
            cpasync16((uint32_t)__cvta_generic_to_shared(&As[s][r][ac]), src, v);
        }
        #pragma unroll
        for (int j = 0; j < NF; j++) {
            int nrow = ar + j * 64;
            bool v = (bn + nrow) < N;
            const __half* srcb = v ? (Bt + (size_t)(bn + nrow) * Kd + k0 + ac) : Bt;
            cpasync16((uint32_t)__cvta_generic_to_shared(&Bs[s][nrow][ac]), srcb, v);
        }
        asm volatile("cp.async.commit_group;\n");
    };

    auto compute = [&](int s) {
        #pragma unroll
        for (int k0 = 0; k0 < 32; k0 += 16) {
            uint32_t a[MF][4], bf[4*NF][2];
            #pragma unroll
            for (int i = 0; i < MF; i++) {
                int r = wm * MF * 16 + i * 16 + g;
                a[i][0] = *(const uint32_t*)&As[s][r    ][k0 + 2*tg    ];
                a[i][1] = *(const uint32_t*)&As[s][r + 8][k0 + 2*tg    ];
                a[i][2] = *(const uint32_t*)&As[s][r    ][k0 + 2*tg + 8];
                a[i][3] = *(const uint32_t*)&As[s][r + 8][k0 + 2*tg + 8];
            }
            #pragma unroll
            for (int j = 0; j < 4*NF; j++) {
                int col = wn * NF * 32 + j * 8 + g;
                bf[j][0] = *(const uint32_t*)&Bs[s][col][k0 + 2*tg    ];
                bf[j][1] = *(const uint32_t*)&Bs[s][col][k0 + 2*tg + 8];
            }
            #pragma unroll
            for (int i = 0; i < MF; i++)
                #pragma unroll
                for (int j = 0; j < 4*NF; j++)
                    asm volatile(
                        "mma.sync.aligned.m16n8k16.row.col.f32.f16.f16.f32 "
                        "{%0,%1,%2,%3},{%4,%5,%6,%7},{%8,%9},{%0,%1,%2,%3};\n"
                        : "+f"(c[i][j][0]), "+f"(c[i][j][1]),
                          "+f"(c[i][j][2]), "+f"(c[i][j][3])
                        : "r"(a[i][0]), "r"(a[i][1]), "r"(a[i][2]), "r"(a[i][3]),
                          "r"(bf[j][0]), "r"(bf[j][1]));
        }
    };

    issue(0, 0);
    issue(1, 32);
    int st = 0;
    for (int kt = 0; kt < nk; kt++) {
        asm volatile("cp.async.wait_group 1;\n");
        __syncthreads();
        compute(st);
        int nx = kt + 2;
        int ws = st + 2; if (ws >= 3) ws -= 3;
        if (nx < nk) issue(ws, nx << 5);
        else asm volatile("cp.async.commit_group;\n");
        if (++st == 3) st = 0;
    }

    __half* Ch = (__half*)Cv;
    float*  Cf = (float*)Cv;
    #pragma unroll
    for (int i = 0; i < MF; i++) {
        int r0 = bm + wm * MF * 16 + i * 16 + g;
        #pragma unroll
        for (int j = 0; j < 4*NF; j++) {
            int col = bn + wn * NF * 32 + j * 8 + 2 * tg;
            if (col < N) {
                if (r0 < M) {
                    float v0 = c[i][j][0], v1 = c[i][j][1];
                    if (LEAKY) { v0 = v0 > 0.f ? v0 : 0.1f*v0; v1 = v1 > 0.f ? v1 : 0.1f*v1; }
                    if (OUTHALF) *(__half2*)&Ch[(size_t)r0 * N + col] = __floats2half2_rn(v0, v1);
                    else { Cf[(size_t)r0 * N + col] = v0; Cf[(size_t)r0 * N + col + 1] = v1; }
                }
                if (r0 + 8 < M) {
                    float v2 = c[i][j][2], v3 = c[i][j][3];
                    if (LEAKY) { v2 = v2 > 0.f ? v2 : 0.1f*v2; v3 = v3 > 0.f ? v3 : 0.1f*v3; }
                    if (OUTHALF) *(__half2*)&Ch[(size_t)(r0+8) * N + col] = __floats2half2_rn(v2, v3);
                    else { Cf[(size_t)(r0+8) * N + col] = v2; Cf[(size_t)(r0+8) * N + col + 1] = v3; }
                }
            }
        }
    }

    if (STATS) {
        float wmax = 0.f;
        if (wn == 0) {
            #pragma unroll
            for (int i = 0; i < MF; i++) {
                float sl = 0.f, sh = 0.f, ml = 0.f, mh = 0.f;
                #pragma unroll
                for (int j = 0; j < 4*NF; j++) {
                    sl += c[i][j][0] + c[i][j][1];
                    sh += c[i][j][2] + c[i][j][3];
                    ml = fmaxf(ml, fmaxf(c[i][j][0], c[i][j][1]));
                    mh = fmaxf(mh, fmaxf(c[i][j][2], c[i][j][3]));
                }
                sl += __shfl_xor_sync(0xffffffffu, sl, 1);
                sl += __shfl_xor_sync(0xffffffffu, sl, 2);
                sh += __shfl_xor_sync(0xffffffffu, sh, 1);
                sh += __shfl_xor_sync(0xffffffffu, sh, 2);
                ml = fmaxf(ml, __shfl_xor_sync(0xffffffffu, ml, 1));
                ml = fmaxf(ml, __shfl_xor_sync(0xffffffffu, ml, 2));
                mh = fmaxf(mh, __shfl_xor_sync(0xffffffffu, mh, 1));
                mh = fmaxf(mh, __shfl_xor_sync(0xffffffffu, mh, 2));
                int r0 = bm + wm * MF * 16 + i * 16 + g;
                if (tg == 0) {
                    if (r0 < M)     rowsum[r0]     = sl;
                    if (r0 + 8 < M) rowsum[r0 + 8] = sh;
                }
                wmax = fmaxf(wmax, fmaxf(ml, mh));
            }
        }
        #pragma unroll
        for (int o = 16; o; o >>= 1)
            wmax = fmaxf(wmax, __shfl_xor_sync(0xffffffffu, wmax, o));
        if (lane == 0) swm[warp] = wmax;
        __syncthreads();
        if (tid == 0) {
            float bmv = swm[0];
            #pragma unroll
            for (int ww = 1; ww < 8; ww++) bmv = fmaxf(bmv, swm[ww]);
            atomicMax(gmaxp, __float_as_int(fmaxf(bmv, 0.f)));
        }
    }
}

// ---------------- detection head: float4 neighbor accumulation -------------------
__global__ void scores_kernel(const int* __restrict__ neigh, const float* __restrict__ ff,
                              const float* __restrict__ rowsum,
                              float* __restrict__ out_fnorm, float* __restrict__ out_scores)
{
    int warp = (blockIdx.x*blockDim.x + threadIdx.x) >> 5;
    int lane = threadIdx.x & 31;
    if (warp >= N0_) return;
    float fraw = ff[(size_t)warp*32 + lane];
    float s2 = fraw*fraw;
    #pragma unroll
    for (int o = 16; o; o >>= 1) s2 += __shfl_xor_sync(0xffffffffu, s2, o);
    float nrm = fmaxf(sqrtf(s2), 1e-12f);
    out_fnorm[(size_t)warp*32 + lane] = fraw / nrm;

    float inv = 1.0f / (__int_as_float(g_gmax) + 1e-6f);
    int myidx = neigh[(size_t)warp*32 + lane];

    int nz = (rowsum[myidx] != 0.f) ? 1 : 0;
    #pragma unroll
    for (int o = 16; o; o >>= 1) nz += __shfl_xor_sync(0xffffffffu, nz, o);
    float nnumf = (float)(nz < 1 ? 1 : nz);

    const int c4 = lane & 7, kg = lane >> 3;
    float4 sum4 = make_float4(0.f,0.f,0.f,0.f);
    float4 max4 = make_float4(-1e30f,-1e30f,-1e30f,-1e30f);
    #pragma unroll
    for (int i = 0; i < 8; i++) {
        int idx = __shfl_sync(0xffffffffu, myidx, i*4 + kg);
        float4 v = *(const float4*)(ff + (size_t)idx*32 + c4*4);
        sum4.x += v.x; sum4.y += v.y; sum4.z += v.z; sum4.w += v.w;
        max4.x = fmaxf(max4.x, v.x); max4.y = fmaxf(max4.y, v.y);
        max4.z = fmaxf(max4.z, v.z); max4.w = fmaxf(max4.w, v.w);
    }
    #pragma unroll
    for (int o = 8; o <= 16; o <<= 1) {
        sum4.x += __shfl_xor_sync(0xffffffffu, sum4.x, o);
        sum4.y += __shfl_xor_sync(0xffffffffu, sum4.y, o);
        sum4.z += __shfl_xor_sync(0xffffffffu, sum4.z, o);
        sum4.w += __shfl_xor_sync(0xffffffffu, sum4.w, o);
        max4.x = fmaxf(max4.x, __shfl_xor_sync(0xffffffffu, max4.x, o));
        max4.y = fmaxf(max4.y, __shfl_xor_sync(0xffffffffu, max4.y, o));
        max4.z = fmaxf(max4.z, __shfl_xor_sync(0xffffffffu, max4.z, o));
        max4.w = fmaxf(max4.w, __shfl_xor_sync(0xffffffffu, max4.w, o));
    }
    int src = lane >> 2;
    float sx = __shfl_sync(0xffffffffu, sum4.x, src);
    float sy = __shfl_sync(0xffffffffu, sum4.y, src);
    float sz = __shfl_sync(0xffffffffu, sum4.z, src);
    float sw = __shfl_sync(0xffffffffu, sum4.w, src);
    float mx = __shfl_sync(0xffffffffu, max4.x, src);
    float my = __shfl_sync(0xffffffffu, max4.y, src);
    float mz = __shfl_sync(0xffffffffu, max4.z, src);
    float mw = __shfl_sync(0xffffffffu, max4.w, src);
    int comp = lane & 3;
    float msum = (comp == 0) ? sx : (comp == 1) ? sy : (comp == 2) ? sz : sw;
    float mraw = (comp == 0) ? mx : (comp == 1) ? my : (comp == 2) ? mz : mw;

    float f = fraw * inv;
    float mean = msum * inv / nnumf;
    float nmax = mraw * inv;
    float x = f - mean;
    float lms = fmaxf(x, 0.f) + log1pf(expf(-fabsf(x)));
    float dmax = f;
    #pragma unroll
    for (int o = 16; o; o >>= 1) dmax = fmaxf(dmax, __shfl_xor_sync(0xffffffffu, dmax, o));
    float sc = lms * f / (1e-6f + dmax);
    float det = (f == nmax) ? 1.f : 0.f;
    #pragma unroll
    for (int o = 16; o; o >>= 1) {
        sc  = fmaxf(sc,  __shfl_xor_sync(0xffffffffu, sc, o));
        det = fmaxf(det, __shfl_xor_sync(0xffffffffu, det, o));
    }
    if (lane == 0) out_scores[warp] = sc * det;
}

// ---------------- launch ----------------------------------------------------------
extern "C" void kernel_launch(void* const* d_in, const int* in_sizes, int n_in,
                              void* d_out, int out_size)
{
    const float* features   = (const float*)d_in[0];
    const float* points0    = (const float*)d_in[1];
    const float* points1    = (const float*)d_in[2];
    const float* points2    = (const float*)d_in[3];
    const int*   neighbors0 = (const int*)d_in[4];
    const int*   neighbors1 = (const int*)d_in[5];
    const int*   neighbors2 = (const int*)d_in[6];
    const int*   pools0     = (const int*)d_in[7];
    const int*   pools1     = (const int*)d_in[8];
    const int*   upsamples0 = (const int*)d_in[9];
    const int*   upsamples1 = (const int*)d_in[10];
    const float* kpoints    = (const float*)d_in[11];
    const float* W1  = (const float*)d_in[12];
    const float* W2  = (const float*)d_in[13];
    const float* W3  = (const float*)d_in[14];
    const float* W4  = (const float*)d_in[15];
    const float* W5  = (const float*)d_in[16];
    const float* Wu1 = (const float*)d_in[17];
    const float* Wu2 = (const float*)d_in[18];
    float* out = (float*)d_out;

    __half *f1,*f2,*f3,*f4,*f5,*fk,*fu1,*wh;
    float *ff,*rowsum;
    int *gmaxp;
    cudaGetSymbolAddress((void**)&f1,  g_f1);
    cudaGetSymbolAddress((void**)&f2,  g_f2);
    cudaGetSymbolAddress((void**)&f3,  g_f3);
    cudaGetSymbolAddress((void**)&f4,  g_f4);
    cudaGetSymbolAddress((void**)&f5,  g_f5);
    cudaGetSymbolAddress((void**)&fk,  g_fk);
    cudaGetSymbolAddress((void**)&fu1, g_fu1);
    cudaGetSymbolAddress((void**)&wh,  g_wh);
    cudaGetSymbolAddress((void**)&ff,  g_ff);
    cudaGetSymbolAddress((void**)&rowsum, g_rowsum);
    cudaGetSymbolAddress((void**)&gmaxp,  g_gmax);

    // dynamic smem: 3 stages * (BM+BN)*40 halfs * 2B
    const int sm11 = 3*( 64+ 64)*40*2;   // 30720
    const int sm12 = 3*( 64+128)*40*2;   // 46080
    cudaFuncSetAttribute(gemm_tc<1,1,true,false,true,false>,  cudaFuncAttributeMaxDynamicSharedMemorySize, sm11);
    cudaFuncSetAttribute(gemm_tc<1,2,true,false,true,false>,  cudaFuncAttributeMaxDynamicSharedMemorySize, sm12);
    cudaFuncSetAttribute(gemm_tc<1,2,true,true,true,false>,   cudaFuncAttributeMaxDynamicSharedMemorySize, sm12);
    cudaFuncSetAttribute(gemm_tc<1,1,false,true,false,true>,  cudaFuncAttributeMaxDynamicSharedMemorySize, sm11);

    // ---- prep (all weight transposes + gmax reset, one launch) ----
    prep_kernel<<<954, 256>>>(W2, W3, W4, W5, Wu1, Wu2, wh);

    // ---- encoder ----
    conv1_kernel<<<N0_/4, 256>>>(points0, neighbors0, features, kpoints, W1, f1);

    gather_mma_kernel<64,8><<<N1_/8, 256>>>(points1, points0, pools0, f1, kpoints, 0.5f, fk, N1_);
    gemm_tc<1,1,true,false,true,false><<<dim3(1,(N1_+63)/64), 256, sm11>>>(fk, wh+WOFF_W2, f2, N1_, 64, 960, nullptr, nullptr, 0, 0, nullptr, nullptr);

    gather_mma_kernel<64,8><<<N1_/8, 256>>>(points1, points1, neighbors1, f2, kpoints, 1.0f, fk, N1_);
    gemm_tc<1,2,true,false,true,false><<<dim3(1,(N1_+63)/64), 256, sm12>>>(fk, wh+WOFF_W3, f3, N1_, 128, 960, nullptr, nullptr, 0, 0, nullptr, nullptr);

    gather_mma_kernel<128,4><<<(N2_+3)/4, 128>>>(points2, points1, pools1, f3, kpoints, 1.0f, fk, N2_);
    gemm_tc<1,1,true,false,true,false><<<dim3(2,(N2_+63)/64), 256, sm11>>>(fk, wh+WOFF_W4, f4, N2_, 128, 1920, nullptr, nullptr, 0, 0, nullptr, nullptr);

    gather_mma_kernel<128,4><<<(N2_+3)/4, 128>>>(points2, points2, neighbors2, f4, kpoints, 2.0f, fk, N2_);
    gemm_tc<1,2,true,false,true,false><<<dim3(2,(N2_+63)/64), 256, sm12>>>(fk, wh+WOFF_W5, f5, N2_, 256, 1920, nullptr, nullptr, 0, 0, nullptr, nullptr);

    // ---- decoder (concat fused into GEMM A-load) ----
    gemm_tc<1,2,true,true,true,false><<<dim3(1,(N1_+63)/64), 256, sm12>>>(f5, wh+WOFF_U1, fu1, N1_, 128, 384,
                                                                          upsamples1, f3, 256, 128, nullptr, nullptr);
    gemm_tc<1,1,false,true,false,true><<<dim3(1,(N0_+63)/64), 256, sm11>>>(fu1, wh+WOFF_U2, ff, N0_, 32, 192,
                                                                           upsamples0, f1, 128, 64, rowsum, gmaxp);

    // ---- detection head + outputs ----
    scores_kernel<<<(N0_ + 7)/8, 256>>>(neighbors0, ff, rowsum, out, out + (size_t)N0_*32);
}

// round 10
// speedup vs baseline: 1.1470x; 1.0929x over previous
#include <cuda_runtime.h>
#include <cuda_fp16.h>
#include <math.h>
#include <stdint.h>

#define N0_ 60000
#define N1_ 15000
#define N2_ 3750
#define K_  32
#define P_  15

// ---------------- intermediate buffers (device globals; no allocations) ----------
__device__ __align__(16) __half g_f1 [N0_*64];        // skip0
__device__ __align__(16) __half g_f2 [N1_*64];
__device__ __align__(16) __half g_f3 [N1_*128];       // skip1
__device__ __align__(16) __half g_f4 [N2_*128];
__device__ __align__(16) __half g_f5 [N2_*256];
__device__ __align__(16) __half g_fk [N1_*P_*64];     // reused by all gathers
__device__ __align__(16) __half g_fu1[N1_*128];
__device__ __align__(16) float  g_ff [N0_*32];
__device__ __align__(16) __half g_wh [976896];        // all transposed half weights
__device__ float g_rowsum[N0_];
__device__ int g_gmax;

#define WOFF_W2  0
#define WOFF_W3  61440
#define WOFF_W4  184320
#define WOFF_W5  430080
#define WOFF_U1  921600
#define WOFF_U2  970752

// ---------------- fused prep: all 6 weight transposes fp32[Kd][N]->half[N][Kd] ----
__global__ __launch_bounds__(256)
void prep_kernel(const float* __restrict__ W2, const float* __restrict__ W3,
                 const float* __restrict__ W4, const float* __restrict__ W5,
                 const float* __restrict__ Wu1, const float* __restrict__ Wu2,
                 __half* __restrict__ wh)
{
    __shared__ float tile[32][33];
    int b = blockIdx.x;
    if (b == 0 && threadIdx.x == 0) g_gmax = 0;
    const float* src; __half* dst; int Kd, N, gx;
    if      (b < 60)  { src=W2;  dst=wh+WOFF_W2; Kd=960;  N=64;  gx=30; }
    else if (b < 180) { src=W3;  dst=wh+WOFF_W3; Kd=960;  N=128; gx=30; b-=60; }
    else if (b < 420) { src=W4;  dst=wh+WOFF_W4; Kd=1920; N=128; gx=60; b-=180; }
    else if (b < 900) { src=W5;  dst=wh+WOFF_W5; Kd=1920; N=256; gx=60; b-=420; }
    else if (b < 948) { src=Wu1; dst=wh+WOFF_U1; Kd=384;  N=128; gx=12; b-=900; }
    else              { src=Wu2; dst=wh+WOFF_U2; Kd=192;  N=32;  gx=6;  b-=948; }
    int kb = (b % gx)*32, nb = (b / gx)*32;
    int tx = threadIdx.x & 31, ty = threadIdx.x >> 5;   // 32 x 8
    #pragma unroll
    for (int r = 0; r < 32; r += 8)
        tile[ty+r][tx] = src[(size_t)(kb+ty+r)*N + nb + tx];
    __syncthreads();
    #pragma unroll
    for (int r = 0; r < 32; r += 8)
        dst[(size_t)(nb+ty+r)*Kd + kb + tx] = __float2half(tile[tx][ty+r]);
}

// ---------------- layer 1: KPConv Cin=1 Cout=64 ----------------------------------
__global__ __launch_bounds__(256)
void conv1_kernel(const float* __restrict__ pts, const int* __restrict__ neigh,
                  const float* __restrict__ feats, const float* __restrict__ kp,
                  const float* __restrict__ W1, __half* __restrict__ out)
{
    const float extent = 0.5f;
    __shared__ float sdiff[4][K_][3];
    __shared__ float sfeat[4][K_];
    __shared__ float sinfl[4][K_*P_];
    __shared__ float sfk[4][P_];
    int pt = threadIdx.x >> 6;
    int t  = threadIdx.x & 63;
    int n  = blockIdx.x * 4 + pt;
    if (t < K_) {
        int idx = neigh[n*K_+t];
        float qx = pts[n*3+0], qy = pts[n*3+1], qz = pts[n*3+2];
        sdiff[pt][t][0] = pts[idx*3+0]-qx;
        sdiff[pt][t][1] = pts[idx*3+1]-qy;
        sdiff[pt][t][2] = pts[idx*3+2]-qz;
        sfeat[pt][t] = feats[idx];
    }
    __syncthreads();
    for (int i = t; i < K_*P_; i += 64) {
        int k = i / P_, p = i % P_;
        float dx = sdiff[pt][k][0] - kp[p*3+0]*extent;
        float dy = sdiff[pt][k][1] - kp[p*3+1]*extent;
        float dz = sdiff[pt][k][2] - kp[p*3+2]*extent;
        float dist = sqrtf(dx*dx+dy*dy+dz*dz);
        sinfl[pt][i] = fmaxf(0.f, 1.f - dist/extent);
    }
    __syncthreads();
    if (t < P_) {
        float acc = 0.f;
        #pragma unroll
        for (int k = 0; k < K_; k++) acc += sinfl[pt][k*P_+t]*sfeat[pt][k];
        sfk[pt][t] = acc;
    }
    __syncthreads();
    float acc = 0.f;
    #pragma unroll
    for (int p = 0; p < P_; p++) acc += sfk[pt][p]*W1[p*64+t];
    out[n*64+t] = __float2half(acc > 0.f ? acc : 0.1f*acc);
}

// ---------------- tensor-core gather (verified R6/R7) -----------------------------
__device__ __forceinline__ void ldsm4t(uint32_t& r0, uint32_t& r1, uint32_t& r2,
                                       uint32_t& r3, uint32_t addr)
{
    asm volatile("ldmatrix.sync.aligned.m8n8.x4.trans.shared.b16 {%0,%1,%2,%3}, [%4];"
                 : "=r"(r0), "=r"(r1), "=r"(r2), "=r"(r3) : "r"(addr));
}

template<int CIN, int WPB>
__global__ __launch_bounds__(32*WPB)
void gather_mma_kernel(const float* __restrict__ qpts, const float* __restrict__ spts,
                       const int* __restrict__ neigh, const __half* __restrict__ feats,
                       const float* __restrict__ kp, float extent,
                       __half* __restrict__ fk, int Npts)
{
    constexpr int STR = CIN + 8;
    constexpr int MT  = CIN / 16;
    __shared__ __half nf[WPB][32][STR];
    __shared__ float  sdiff[WPB][32][4];
    __shared__ int    sidx[WPB][32];

    const int w    = threadIdx.x >> 5;
    const int lane = threadIdx.x & 31;
    const int n    = blockIdx.x * WPB + w;
    if (n >= Npts) return;
    const int g = lane >> 2, t4 = lane & 3;

    {
        int idx = neigh[n*K_ + lane];
        sidx[w][lane] = idx;
        float qx = qpts[n*3+0], qy = qpts[n*3+1], qz = qpts[n*3+2];
        sdiff[w][lane][0] = spts[idx*3+0]-qx;
        sdiff[w][lane][1] = spts[idx*3+1]-qy;
        sdiff[w][lane][2] = spts[idx*3+2]-qz;
    }
    __syncwarp();

    if (CIN == 64) {
        #pragma unroll
        for (int r = 0; r < 8; r++) {
            int row = r*4 + (lane>>3);
            int ch  = (lane&7)*8;
            uint4 v = *(const uint4*)(feats + (size_t)sidx[w][row]*CIN + ch);
            *(uint4*)&nf[w][row][ch] = v;
        }
    } else {
        #pragma unroll
        for (int r = 0; r < 16; r++) {
            int row = r*2 + (lane>>4);
            int ch  = (lane&15)*8;
            uint4 v = *(const uint4*)(feats + (size_t)sidx[w][row]*CIN + ch);
            *(uint4*)&nf[w][row][ch] = v;
        }
    }

    const float inv_e = 1.0f / extent;
    uint32_t bfr[2][2][2];
    #pragma unroll
    for (int nt = 0; nt < 2; nt++) {
        int p = nt*8 + g;
        bool pv = p < P_;
        float px = 0.f, py = 0.f, pz = 0.f;
        if (pv) {
            px = kp[p*3+0]*extent; py = kp[p*3+1]*extent; pz = kp[p*3+2]*extent;
        }
        #pragma unroll
        for (int ks = 0; ks < 2; ks++) {
            int kb = ks*16 + 2*t4;
            float v[4];
            #pragma unroll
            for (int j = 0; j < 4; j++) {
                int k = kb + (j>>1)*8 + (j&1);
                float dx = sdiff[w][k][0]-px;
                float dy = sdiff[w][k][1]-py;
                float dz = sdiff[w][k][2]-pz;
                float d = sqrtf(dx*dx+dy*dy+dz*dz);
                v[j] = pv ? fmaxf(0.f, 1.f - d*inv_e) : 0.f;
            }
            __half2 h0 = __floats2half2_rn(v[0], v[1]);
            __half2 h1 = __floats2half2_rn(v[2], v[3]);
            bfr[nt][ks][0] = *reinterpret_cast<uint32_t*>(&h0);
            bfr[nt][ks][1] = *reinterpret_cast<uint32_t*>(&h1);
        }
    }
    __syncwarp();

    float d[MT][2][4];
    #pragma unroll
    for (int mt = 0; mt < MT; mt++)
        #pragma unroll
        for (int nt = 0; nt < 2; nt++) {
            d[mt][nt][0]=0.f; d[mt][nt][1]=0.f; d[mt][nt][2]=0.f; d[mt][nt][3]=0.f;
        }
    uint32_t nf_base = (uint32_t)__cvta_generic_to_shared(&nf[w][0][0]);
    const int grp = lane >> 3, jj = lane & 7;
    #pragma unroll
    for (int mt = 0; mt < MT; mt++) {
        #pragma unroll
        for (int ks = 0; ks < 2; ks++) {
            int krow = ks*16 + ((grp & 2) ? 8 : 0) + jj;
            int mcol = mt*16 + ((grp & 1) ? 8 : 0);
            uint32_t addr = nf_base + (uint32_t)(krow*STR + mcol)*2u;
            uint32_t a0,a1,a2,a3;
            ldsm4t(a0,a1,a2,a3, addr);
            #pragma unroll
            for (int nt = 0; nt < 2; nt++)
                asm volatile(
                    "mma.sync.aligned.m16n8k16.row.col.f32.f16.f16.f32 "
                    "{%0,%1,%2,%3},{%4,%5,%6,%7},{%8,%9},{%0,%1,%2,%3};\n"
                    : "+f"(d[mt][nt][0]), "+f"(d[mt][nt][1]),
                      "+f"(d[mt][nt][2]), "+f"(d[mt][nt][3])
                    : "r"(a0), "r"(a1), "r"(a2), "r"(a3),
                      "r"(bfr[nt][ks][0]), "r"(bfr[nt][ks][1]));
        }
    }
    __syncwarp();

    #pragma unroll
    for (int mt = 0; mt < MT; mt++) {
        int c = mt*16 + g;
        #pragma unroll
        for (int nt = 0; nt < 2; nt++) {
            int p0 = nt*8 + 2*t4;
            nf[w][p0  ][c  ] = __float2half(d[mt][nt][0]);
            nf[w][p0+1][c  ] = __float2half(d[mt][nt][1]);
            nf[w][p0  ][c+8] = __float2half(d[mt][nt][2]);
            nf[w][p0+1][c+8] = __float2half(d[mt][nt][3]);
        }
    }
    __syncwarp();
    constexpr int CH = P_ * CIN / 8;
    #pragma unroll
    for (int cid = lane; cid < CH; cid += 32) {
        int p = cid / (CIN/8), cc = cid % (CIN/8);
        uint4 v = *(const uint4*)&nf[w][p][cc*8];
        *(uint4*)(fk + (size_t)n*(P_*CIN) + cid*8) = v;
    }
}

// ================= fp16 tensor-core GEMM: BK=64, 3-stage cp.async ================
__device__ __forceinline__ void cpasync16(uint32_t dst, const void* src, bool valid) {
    int sz = valid ? 16 : 0;
    asm volatile("cp.async.cg.shared.global [%0], [%1], 16, %2;\n"
                 :: "r"(dst), "l"(src), "r"(sz));
}

template<int MF, int NF, bool LEAKY, bool CAT, bool OUTHALF, bool STATS>
__global__ __launch_bounds__(256)
void gemm_tc(const __half* __restrict__ A, const __half* __restrict__ Bt,
             void* __restrict__ Cv, int M, int N, int Kd,
             const int* __restrict__ upidx, const __half* __restrict__ Askip,
             int c_up, int c_skip, float* __restrict__ rowsum, int* __restrict__ gmaxp)
{
    constexpr int BM = MF * 64, BN = NF * 64;
    constexpr int AI = BM / 32;          // A 16B-chunks per thread per stage
    constexpr int BI = BN / 32;          // B chunks per thread per stage
    extern __shared__ __align__(16) __half dynsm[];
    __half* As = dynsm;                  // 3 stages of [BM][72]
    __half* Bs = dynsm + 3*BM*72;        // 3 stages of [BN][72]
    __shared__ float swm[8];

    const int bm = blockIdx.y * BM, bn = blockIdx.x * BN;
    const int tid  = threadIdx.x;
    const int warp = tid >> 5, lane = tid & 31;
    const int wm = warp >> 1, wn = warp & 1;
    const int g  = lane >> 2, tg = lane & 3;

    float c[MF][4*NF][4];
    #pragma unroll
    for (int i = 0; i < MF; i++)
        #pragma unroll
        for (int j = 0; j < 4*NF; j++) {
            c[i][j][0]=0.f; c[i][j][1]=0.f; c[i][j][2]=0.f; c[i][j][3]=0.f;
        }

    const int arow = tid >> 3;           // 0..31, + i*32
    const int akoff = (tid & 7) * 8;     // 0..56 halfs

    int ridx[AI];
    if (CAT) {
        #pragma unroll
        for (int i = 0; i < AI; i++) {
            int r = bm + arow + i * 32;
            ridx[i] = (r < M) ? upidx[r] : 0;
        }
    }

    const int nk = Kd >> 6;

    auto issue = [&](int s, int k0) {
        __half* Ast = As + s * (BM*72);
        #pragma unroll
        for (int i = 0; i < AI; i++) {
            int r = arow + i * 32;
            bool v = (bm + r) < M;
            int kc = k0 + akoff;
            const __half* src;
            if (CAT) {
                src = (kc < c_up) ? (A + (size_t)ridx[i] * c_up + kc)
                                  : (Askip + (size_t)(bm + r) * c_skip + (kc - c_up));
                if (!v) src = A;
            } else {
                src = v ? (A + (size_t)(bm + r) * Kd + kc) : A;
            }
            cpasync16((uint32_t)__cvta_generic_to_shared(&Ast[r*72 + akoff]), src, v);
        }
        __half* Bst = Bs + s * (BN*72);
        #pragma unroll
        for (int i = 0; i < BI; i++) {
            int r = arow + i * 32;
            bool v = (bn + r) < N;
            const __half* srcb = v ? (Bt + (size_t)(bn + r) * Kd + k0 + akoff) : Bt;
            cpasync16((uint32_t)__cvta_generic_to_shared(&Bst[r*72 + akoff]), srcb, v);
        }
        asm volatile("cp.async.commit_group;\n");
    };

    auto compute = [&](int s) {
        const __half* Ast = As + s * (BM*72);
        const __half* Bst = Bs + s * (BN*72);
        #pragma unroll
        for (int k0 = 0; k0 < 64; k0 += 16) {
            uint32_t a[MF][4], bf[4*NF][2];
            #pragma unroll
            for (int i = 0; i < MF; i++) {
                int r = wm * MF * 16 + i * 16 + g;
                a[i][0] = *(const uint32_t*)&Ast[r*72     + k0 + 2*tg    ];
                a[i][1] = *(const uint32_t*)&Ast[(r+8)*72 + k0 + 2*tg    ];
                a[i][2] = *(const uint32_t*)&Ast[r*72     + k0 + 2*tg + 8];
                a[i][3] = *(const uint32_t*)&Ast[(r+8)*72 + k0 + 2*tg + 8];
            }
            #pragma unroll
            for (int j = 0; j < 4*NF; j++) {
                int col = wn * NF * 32 + j * 8 + g;
                bf[j][0] = *(const uint32_t*)&Bst[col*72 + k0 + 2*tg    ];
                bf[j][1] = *(const uint32_t*)&Bst[col*72 + k0 + 2*tg + 8];
            }
            #pragma unroll
            for (int i = 0; i < MF; i++)
                #pragma unroll
                for (int j = 0; j < 4*NF; j++)
                    asm volatile(
                        "mma.sync.aligned.m16n8k16.row.col.f32.f16.f16.f32 "
                        "{%0,%1,%2,%3},{%4,%5,%6,%7},{%8,%9},{%0,%1,%2,%3};\n"
                        : "+f"(c[i][j][0]), "+f"(c[i][j][1]),
                          "+f"(c[i][j][2]), "+f"(c[i][j][3])
                        : "r"(a[i][0]), "r"(a[i][1]), "r"(a[i][2]), "r"(a[i][3]),
                          "r"(bf[j][0]), "r"(bf[j][1]));
        }
    };

    issue(0, 0);
    if (nk > 1) issue(1, 64);
    else asm volatile("cp.async.commit_group;\n");
    int st = 0;
    for (int kt = 0; kt < nk; kt++) {
        asm volatile("cp.async.wait_group 1;\n");
        __syncthreads();
        compute(st);
        int nx = kt + 2;
        int ws = st + 2; if (ws >= 3) ws -= 3;
        if (nx < nk) issue(ws, nx << 6);
        else asm volatile("cp.async.commit_group;\n");
        if (++st == 3) st = 0;
    }

    __half* Ch = (__half*)Cv;
    float*  Cf = (float*)Cv;
    #pragma unroll
    for (int i = 0; i < MF; i++) {
        int r0 = bm + wm * MF * 16 + i * 16 + g;
        #pragma unroll
        for (int j = 0; j < 4*NF; j++) {
            int col = bn + wn * NF * 32 + j * 8 + 2 * tg;
            if (col < N) {
                if (r0 < M) {
                    float v0 = c[i][j][0], v1 = c[i][j][1];
                    if (LEAKY) { v0 = v0 > 0.f ? v0 : 0.1f*v0; v1 = v1 > 0.f ? v1 : 0.1f*v1; }
                    if (OUTHALF) *(__half2*)&Ch[(size_t)r0 * N + col] = __floats2half2_rn(v0, v1);
                    else { Cf[(size_t)r0 * N + col] = v0; Cf[(size_t)r0 * N + col + 1] = v1; }
                }
                if (r0 + 8 < M) {
                    float v2 = c[i][j][2], v3 = c[i][j][3];
                    if (LEAKY) { v2 = v2 > 0.f ? v2 : 0.1f*v2; v3 = v3 > 0.f ? v3 : 0.1f*v3; }
                    if (OUTHALF) *(__half2*)&Ch[(size_t)(r0+8) * N + col] = __floats2half2_rn(v2, v3);
                    else { Cf[(size_t)(r0+8) * N + col] = v2; Cf[(size_t)(r0+8) * N + col + 1] = v3; }
                }
            }
        }
    }

    if (STATS) {
        float wmax = 0.f;
        if (wn == 0) {
            #pragma unroll
            for (int i = 0; i < MF; i++) {
                float sl = 0.f, sh = 0.f, ml = 0.f, mh = 0.f;
                #pragma unroll
                for (int j = 0; j < 4*NF; j++) {
                    sl += c[i][j][0] + c[i][j][1];
                    sh += c[i][j][2] + c[i][j][3];
                    ml = fmaxf(ml, fmaxf(c[i][j][0], c[i][j][1]));
                    mh = fmaxf(mh, fmaxf(c[i][j][2], c[i][j][3]));
                }
                sl += __shfl_xor_sync(0xffffffffu, sl, 1);
                sl += __shfl_xor_sync(0xffffffffu, sl, 2);
                sh += __shfl_xor_sync(0xffffffffu, sh, 1);
                sh += __shfl_xor_sync(0xffffffffu, sh, 2);
                ml = fmaxf(ml, __shfl_xor_sync(0xffffffffu, ml, 1));
                ml = fmaxf(ml, __shfl_xor_sync(0xffffffffu, ml, 2));
                mh = fmaxf(mh, __shfl_xor_sync(0xffffffffu, mh, 1));
                mh = fmaxf(mh, __shfl_xor_sync(0xffffffffu, mh, 2));
                int r0 = bm + wm * MF * 16 + i * 16 + g;
                if (tg == 0) {
                    if (r0 < M)     rowsum[r0]     = sl;
                    if (r0 + 8 < M) rowsum[r0 + 8] = sh;
                }
                wmax = fmaxf(wmax, fmaxf(ml, mh));
            }
        }
        #pragma unroll
        for (int o = 16; o; o >>= 1)
            wmax = fmaxf(wmax, __shfl_xor_sync(0xffffffffu, wmax, o));
        if (lane == 0) swm[warp] = wmax;
        __syncthreads();
        if (tid == 0) {
            float bmv = swm[0];
            #pragma unroll
            for (int ww = 1; ww < 8; ww++) bmv = fmaxf(bmv, swm[ww]);
            atomicMax(gmaxp, __float_as_int(fmaxf(bmv, 0.f)));
        }
    }
}

// ---------------- detection head: float4 neighbor accumulation -------------------
__global__ void scores_kernel(const int* __restrict__ neigh, const float* __restrict__ ff,
                              const float* __restrict__ rowsum,
                              float* __restrict__ out_fnorm, float* __restrict__ out_scores)
{
    int warp = (blockIdx.x*blockDim.x + threadIdx.x) >> 5;
    int lane = threadIdx.x & 31;
    if (warp >= N0_) return;
    float fraw = ff[(size_t)warp*32 + lane];
    float s2 = fraw*fraw;
    #pragma unroll
    for (int o = 16; o; o >>= 1) s2 += __shfl_xor_sync(0xffffffffu, s2, o);
    float nrm = fmaxf(sqrtf(s2), 1e-12f);
    out_fnorm[(size_t)warp*32 + lane] = fraw / nrm;

    float inv = 1.0f / (__int_as_float(g_gmax) + 1e-6f);
    int myidx = neigh[(size_t)warp*32 + lane];

    int nz = (rowsum[myidx] != 0.f) ? 1 : 0;
    #pragma unroll
    for (int o = 16; o; o >>= 1) nz += __shfl_xor_sync(0xffffffffu, nz, o);
    float nnumf = (float)(nz < 1 ? 1 : nz);

    const int c4 = lane & 7, kg = lane >> 3;
    float4 sum4 = make_float4(0.f,0.f,0.f,0.f);
    float4 max4 = make_float4(-1e30f,-1e30f,-1e30f,-1e30f);
    #pragma unroll
    for (int i = 0; i < 8; i++) {
        int idx = __shfl_sync(0xffffffffu, myidx, i*4 + kg);
        float4 v = *(const float4*)(ff + (size_t)idx*32 + c4*4);
        sum4.x += v.x; sum4.y += v.y; sum4.z += v.z; sum4.w += v.w;
        max4.x = fmaxf(max4.x, v.x); max4.y = fmaxf(max4.y, v.y);
        max4.z = fmaxf(max4.z, v.z); max4.w = fmaxf(max4.w, v.w);
    }
    #pragma unroll
    for (int o = 8; o <= 16; o <<= 1) {
        sum4.x += __shfl_xor_sync(0xffffffffu, sum4.x, o);
        sum4.y += __shfl_xor_sync(0xffffffffu, sum4.y, o);
        sum4.z += __shfl_xor_sync(0xffffffffu, sum4.z, o);
        sum4.w += __shfl_xor_sync(0xffffffffu, sum4.w, o);
        max4.x = fmaxf(max4.x, __shfl_xor_sync(0xffffffffu, max4.x, o));
        max4.y = fmaxf(max4.y, __shfl_xor_sync(0xffffffffu, max4.y, o));
        max4.z = fmaxf(max4.z, __shfl_xor_sync(0xffffffffu, max4.z, o));
        max4.w = fmaxf(max4.w, __shfl_xor_sync(0xffffffffu, max4.w, o));
    }
    int src = lane >> 2;
    float sx = __shfl_sync(0xffffffffu, sum4.x, src);
    float sy = __shfl_sync(0xffffffffu, sum4.y, src);
    float sz = __shfl_sync(0xffffffffu, sum4.z, src);
    float sw = __shfl_sync(0xffffffffu, sum4.w, src);
    float mx = __shfl_sync(0xffffffffu, max4.x, src);
    float my = __shfl_sync(0xffffffffu, max4.y, src);
    float mz = __shfl_sync(0xffffffffu, max4.z, src);
    float mw = __shfl_sync(0xffffffffu, max4.w, src);
    int comp = lane & 3;
    float msum = (comp == 0) ? sx : (comp == 1) ? sy : (comp == 2) ? sz : sw;
    float mraw = (comp == 0) ? mx : (comp == 1) ? my : (comp == 2) ? mz : mw;

    float f = fraw * inv;
    float mean = msum * inv / nnumf;
    float nmax = mraw * inv;
    float x = f - mean;
    float lms = fmaxf(x, 0.f) + log1pf(expf(-fabsf(x)));
    float dmax = f;
    #pragma unroll
    for (int o = 16; o; o >>= 1) dmax = fmaxf(dmax, __shfl_xor_sync(0xffffffffu, dmax, o));
    float sc = lms * f / (1e-6f + dmax);
    float det = (f == nmax) ? 1.f : 0.f;
    #pragma unroll
    for (int o = 16; o; o >>= 1) {
        sc  = fmaxf(sc,  __shfl_xor_sync(0xffffffffu, sc, o));
        det = fmaxf(det, __shfl_xor_sync(0xffffffffu, det, o));
    }
    if (lane == 0) out_scores[warp] = sc * det;
}

// ---------------- launch ----------------------------------------------------------
extern "C" void kernel_launch(void* const* d_in, const int* in_sizes, int n_in,
                              void* d_out, int out_size)
{
    const float* features   = (const float*)d_in[0];
    const float* points0    = (const float*)d_in[1];
    const float* points1    = (const float*)d_in[2];
    const float* points2    = (const float*)d_in[3];
    const int*   neighbors0 = (const int*)d_in[4];
    const int*   neighbors1 = (const int*)d_in[5];
    const int*   neighbors2 = (const int*)d_in[6];
    const int*   pools0     = (const int*)d_in[7];
    const int*   pools1     = (const int*)d_in[8];
    const int*   upsamples0 = (const int*)d_in[9];
    const int*   upsamples1 = (const int*)d_in[10];
    const float* kpoints    = (const float*)d_in[11];
    const float* W1  = (const float*)d_in[12];
    const float* W2  = (const float*)d_in[13];
    const float* W3  = (const float*)d_in[14];
    const float* W4  = (const float*)d_in[15];
    const float* W5  = (const float*)d_in[16];
    const float* Wu1 = (const float*)d_in[17];
    const float* Wu2 = (const float*)d_in[18];
    float* out = (float*)d_out;

    __half *f1,*f2,*f3,*f4,*f5,*fk,*fu1,*wh;
    float *ff,*rowsum;
    int *gmaxp;
    cudaGetSymbolAddress((void**)&f1,  g_f1);
    cudaGetSymbolAddress((void**)&f2,  g_f2);
    cudaGetSymbolAddress((void**)&f3,  g_f3);
    cudaGetSymbolAddress((void**)&f4,  g_f4);
    cudaGetSymbolAddress((void**)&f5,  g_f5);
    cudaGetSymbolAddress((void**)&fk,  g_fk);
    cudaGetSymbolAddress((void**)&fu1, g_fu1);
    cudaGetSymbolAddress((void**)&wh,  g_wh);
    cudaGetSymbolAddress((void**)&ff,  g_ff);
    cudaGetSymbolAddress((void**)&rowsum, g_rowsum);
    cudaGetSymbolAddress((void**)&gmaxp,  g_gmax);

    // dynamic smem: 3 stages * (BM+BN)*72 halfs * 2B
    const int sm21 = 3*(128+ 64)*72*2;   // 82944
    const int sm22 = 3*(128+128)*72*2;   // 110592
    const int sm11 = 3*( 64+ 64)*72*2;   // 55296
    const int sm12 = 3*( 64+128)*72*2;   // 82944
    cudaFuncSetAttribute(gemm_tc<2,1,true,false,true,false>,  cudaFuncAttributeMaxDynamicSharedMemorySize, sm21);
    cudaFuncSetAttribute(gemm_tc<2,2,true,false,true,false>,  cudaFuncAttributeMaxDynamicSharedMemorySize, sm22);
    cudaFuncSetAttribute(gemm_tc<1,1,true,false,true,false>,  cudaFuncAttributeMaxDynamicSharedMemorySize, sm11);
    cudaFuncSetAttribute(gemm_tc<1,2,true,false,true,false>,  cudaFuncAttributeMaxDynamicSharedMemorySize, sm12);
    cudaFuncSetAttribute(gemm_tc<2,2,true,true,true,false>,   cudaFuncAttributeMaxDynamicSharedMemorySize, sm22);
    cudaFuncSetAttribute(gemm_tc<2,1,false,true,false,true>,  cudaFuncAttributeMaxDynamicSharedMemorySize, sm21);

    // ---- prep (all weight transposes + gmax reset, one launch) ----
    prep_kernel<<<954, 256>>>(W2, W3, W4, W5, Wu1, Wu2, wh);

    // ---- encoder ----
    conv1_kernel<<<N0_/4, 256>>>(points0, neighbors0, features, kpoints, W1, f1);

    gather_mma_kernel<64,8><<<N1_/8, 256>>>(points1, points0, pools0, f1, kpoints, 0.5f, fk, N1_);
    gemm_tc<2,1,true,false,true,false><<<dim3(1,(N1_+127)/128), 256, sm21>>>(fk, wh+WOFF_W2, f2, N1_, 64, 960, nullptr, nullptr, 0, 0, nullptr, nullptr);

    gather_mma_kernel<64,8><<<N1_/8, 256>>>(points1, points1, neighbors1, f2, kpoints, 1.0f, fk, N1_);
    gemm_tc<2,2,true,false,true,false><<<dim3(1,(N1_+127)/128), 256, sm22>>>(fk, wh+WOFF_W3, f3, N1_, 128, 960, nullptr, nullptr, 0, 0, nullptr, nullptr);

    gather_mma_kernel<128,4><<<(N2_+3)/4, 128>>>(points2, points1, pools1, f3, kpoints, 1.0f, fk, N2_);
    gemm_tc<1,1,true,false,true,false><<<dim3(2,(N2_+63)/64), 256, sm11>>>(fk, wh+WOFF_W4, f4, N2_, 128, 1920, nullptr, nullptr, 0, 0, nullptr, nullptr);

    gather_mma_kernel<128,4><<<(N2_+3)/4, 128>>>(points2, points2, neighbors2, f4, kpoints, 2.0f, fk, N2_);
    gemm_tc<1,2,true,false,true,false><<<dim3(2,(N2_+63)/64), 256, sm12>>>(fk, wh+WOFF_W5, f5, N2_, 256, 1920, nullptr, nullptr, 0, 0, nullptr, nullptr);

    // ---- decoder (concat fused into GEMM A-load) ----
    gemm_tc<2,2,true,true,true,false><<<dim3(1,(N1_+127)/128), 256, sm22>>>(f5, wh+WOFF_U1, fu1, N1_, 128, 384,
                                                                            upsamples1, f3, 256, 128, nullptr, nullptr);
    gemm_tc<2,1,false,true,false,true><<<dim3(1,(N0_+127)/128), 256, sm21>>>(fu1, wh+WOFF_U2, ff, N0_, 32, 192,
                                                                             upsamples0, f1, 128, 64, rowsum, gmaxp);

    // ---- detection head + outputs ----
    scores_kernel<<<(N0_ + 7)/8, 256>>>(neighbors0, ff, rowsum, out, out + (size_t)N0_*32);
}

// round 12
// speedup vs baseline: 1.1545x; 1.0065x over previous
#include <cuda_runtime.h>
#include <cuda_fp16.h>
#include <math.h>
#include <stdint.h>

#define N0_ 60000
#define N1_ 15000
#define N2_ 3750
#define K_  32
#define P_  15

// ---------------- intermediate buffers (device globals; no allocations) ----------
__device__ __align__(16) __half g_f1 [N0_*64];        // skip0
__device__ __align__(16) __half g_f2 [N1_*64];
__device__ __align__(16) __half g_f3 [N1_*128];       // skip1
__device__ __align__(16) __half g_f4 [N2_*128];
__device__ __align__(16) __half g_f5 [N2_*256];
__device__ __align__(16) __half g_fk [N1_*P_*64];     // reused by all gathers
__device__ __align__(16) __half g_fu1[N1_*128];
__device__ __align__(16) float  g_ff [N0_*32];
__device__ __align__(16) __half g_wh [976896];        // all transposed half weights
__device__ float g_rowsum[N0_];
__device__ int g_gmax;

#define WOFF_W2  0
#define WOFF_W3  61440
#define WOFF_W4  184320
#define WOFF_W5  430080
#define WOFF_U1  921600
#define WOFF_U2  970752

// ---------------- fused prep: all 6 weight transposes fp32[Kd][N]->half[N][Kd] ----
__global__ __launch_bounds__(256)
void prep_kernel(const float* __restrict__ W2, const float* __restrict__ W3,
                 const float* __restrict__ W4, const float* __restrict__ W5,
                 const float* __restrict__ Wu1, const float* __restrict__ Wu2,
                 __half* __restrict__ wh)
{
    __shared__ float tile[32][33];
    int b = blockIdx.x;
    if (b == 0 && threadIdx.x == 0) g_gmax = 0;
    const float* src; __half* dst; int Kd, N, gx;
    if      (b < 60)  { src=W2;  dst=wh+WOFF_W2; Kd=960;  N=64;  gx=30; }
    else if (b < 180) { src=W3;  dst=wh+WOFF_W3; Kd=960;  N=128; gx=30; b-=60; }
    else if (b < 420) { src=W4;  dst=wh+WOFF_W4; Kd=1920; N=128; gx=60; b-=180; }
    else if (b < 900) { src=W5;  dst=wh+WOFF_W5; Kd=1920; N=256; gx=60; b-=420; }
    else if (b < 948) { src=Wu1; dst=wh+WOFF_U1; Kd=384;  N=128; gx=12; b-=900; }
    else              { src=Wu2; dst=wh+WOFF_U2; Kd=192;  N=32;  gx=6;  b-=948; }
    int kb = (b % gx)*32, nb = (b / gx)*32;
    int tx = threadIdx.x & 31, ty = threadIdx.x >> 5;   // 32 x 8
    #pragma unroll
    for (int r = 0; r < 32; r += 8)
        tile[ty+r][tx] = src[(size_t)(kb+ty+r)*N + nb + tx];
    __syncthreads();
    #pragma unroll
    for (int r = 0; r < 32; r += 8)
        dst[(size_t)(nb+ty+r)*Kd + kb + tx] = __float2half(tile[tx][ty+r]);
}

// ---------------- layer 1: KPConv Cin=1 Cout=64 ----------------------------------
__global__ __launch_bounds__(256)
void conv1_kernel(const float* __restrict__ pts, const int* __restrict__ neigh,
                  const float* __restrict__ feats, const float* __restrict__ kp,
                  const float* __restrict__ W1, __half* __restrict__ out)
{
    const float extent = 0.5f;
    __shared__ float sdiff[4][K_][3];
    __shared__ float sfeat[4][K_];
    __shared__ float sinfl[4][K_*P_];
    __shared__ float sfk[4][P_];
    int pt = threadIdx.x >> 6;
    int t  = threadIdx.x & 63;
    int n  = blockIdx.x * 4 + pt;
    if (t < K_) {
        int idx = neigh[n*K_+t];
        float qx = pts[n*3+0], qy = pts[n*3+1], qz = pts[n*3+2];
        sdiff[pt][t][0] = pts[idx*3+0]-qx;
        sdiff[pt][t][1] = pts[idx*3+1]-qy;
        sdiff[pt][t][2] = pts[idx*3+2]-qz;
        sfeat[pt][t] = feats[idx];
    }
    __syncthreads();
    for (int i = t; i < K_*P_; i += 64) {
        int k = i / P_, p = i % P_;
        float dx = sdiff[pt][k][0] - kp[p*3+0]*extent;
        float dy = sdiff[pt][k][1] - kp[p*3+1]*extent;
        float dz = sdiff[pt][k][2] - kp[p*3+2]*extent;
        float dist = sqrtf(dx*dx+dy*dy+dz*dz);
        sinfl[pt][i] = fmaxf(0.f, 1.f - dist/extent);
    }
    __syncthreads();
    if (t < P_) {
        float acc = 0.f;
        #pragma unroll
        for (int k = 0; k < K_; k++) acc += sinfl[pt][k*P_+t]*sfeat[pt][k];
        sfk[pt][t] = acc;
    }
    __syncthreads();
    float acc = 0.f;
    #pragma unroll
    for (int p = 0; p < P_; p++) acc += sfk[pt][p]*W1[p*64+t];
    out[n*64+t] = __float2half(acc > 0.f ? acc : 0.1f*acc);
}

// ---------------- tensor-core gather (verified R6/R7) -----------------------------
__device__ __forceinline__ void ldsm4t(uint32_t& r0, uint32_t& r1, uint32_t& r2,
                                       uint32_t& r3, uint32_t addr)
{
    asm volatile("ldmatrix.sync.aligned.m8n8.x4.trans.shared.b16 {%0,%1,%2,%3}, [%4];"
                 : "=r"(r0), "=r"(r1), "=r"(r2), "=r"(r3) : "r"(addr));
}

template<int CIN, int WPB>
__global__ __launch_bounds__(32*WPB)
void gather_mma_kernel(const float* __restrict__ qpts, const float* __restrict__ spts,
                       const int* __restrict__ neigh, const __half* __restrict__ feats,
                       const float* __restrict__ kp, float extent,
                       __half* __restrict__ fk, int Npts)
{
    constexpr int STR = CIN + 8;
    constexpr int MT  = CIN / 16;
    __shared__ __half nf[WPB][32][STR];
    __shared__ float  sdiff[WPB][32][4];
    __shared__ int    sidx[WPB][32];

    const int w    = threadIdx.x >> 5;
    const int lane = threadIdx.x & 31;
    const int n    = blockIdx.x * WPB + w;
    if (n >= Npts) return;
    const int g = lane >> 2, t4 = lane & 3;

    {
        int idx = neigh[n*K_ + lane];
        sidx[w][lane] = idx;
        float qx = qpts[n*3+0], qy = qpts[n*3+1], qz = qpts[n*3+2];
        sdiff[w][lane][0] = spts[idx*3+0]-qx;
        sdiff[w][lane][1] = spts[idx*3+1]-qy;
        sdiff[w][lane][2] = spts[idx*3+2]-qz;
    }
    __syncwarp();

    if (CIN == 64) {
        #pragma unroll
        for (int r = 0; r < 8; r++) {
            int row = r*4 + (lane>>3);
            int ch  = (lane&7)*8;
            uint4 v = *(const uint4*)(feats + (size_t)sidx[w][row]*CIN + ch);
            *(uint4*)&nf[w][row][ch] = v;
        }
    } else {
        #pragma unroll
        for (int r = 0; r < 16; r++) {
            int row = r*2 + (lane>>4);
            int ch  = (lane&15)*8;
            uint4 v = *(const uint4*)(feats + (size_t)sidx[w][row]*CIN + ch);
            *(uint4*)&nf[w][row][ch] = v;
        }
    }

    const float inv_e = 1.0f / extent;
    uint32_t bfr[2][2][2];
    #pragma unroll
    for (int nt = 0; nt < 2; nt++) {
        int p = nt*8 + g;
        bool pv = p < P_;
        float px = 0.f, py = 0.f, pz = 0.f;
        if (pv) {
            px = kp[p*3+0]*extent; py = kp[p*3+1]*extent; pz = kp[p*3+2]*extent;
        }
        #pragma unroll
        for (int ks = 0; ks < 2; ks++) {
            int kb = ks*16 + 2*t4;
            float v[4];
            #pragma unroll
            for (int j = 0; j < 4; j++) {
                int k = kb + (j>>1)*8 + (j&1);
                float dx = sdiff[w][k][0]-px;
                float dy = sdiff[w][k][1]-py;
                float dz = sdiff[w][k][2]-pz;
                float d = sqrtf(dx*dx+dy*dy+dz*dz);
                v[j] = pv ? fmaxf(0.f, 1.f - d*inv_e) : 0.f;
            }
            __half2 h0 = __floats2half2_rn(v[0], v[1]);
            __half2 h1 = __floats2half2_rn(v[2], v[3]);
            bfr[nt][ks][0] = *reinterpret_cast<uint32_t*>(&h0);
            bfr[nt][ks][1] = *reinterpret_cast<uint32_t*>(&h1);
        }
    }
    __syncwarp();

    float d[MT][2][4];
    #pragma unroll
    for (int mt = 0; mt < MT; mt++)
        #pragma unroll
        for (int nt = 0; nt < 2; nt++) {
            d[mt][nt][0]=0.f; d[mt][nt][1]=0.f; d[mt][nt][2]=0.f; d[mt][nt][3]=0.f;
        }
    uint32_t nf_base = (uint32_t)__cvta_generic_to_shared(&nf[w][0][0]);
    const int grp = lane >> 3, jj = lane & 7;
    #pragma unroll
    for (int mt = 0; mt < MT; mt++) {
        #pragma unroll
        for (int ks = 0; ks < 2; ks++) {
            int krow = ks*16 + ((grp & 2) ? 8 : 0) + jj;
            int mcol = mt*16 + ((grp & 1) ? 8 : 0);
            uint32_t addr = nf_base + (uint32_t)(krow*STR + mcol)*2u;
            uint32_t a0,a1,a2,a3;
            ldsm4t(a0,a1,a2,a3, addr);
            #pragma unroll
            for (int nt = 0; nt < 2; nt++)
                asm volatile(
                    "mma.sync.aligned.m16n8k16.row.col.f32.f16.f16.f32 "
                    "{%0,%1,%2,%3},{%4,%5,%6,%7},{%8,%9},{%0,%1,%2,%3};\n"
                    : "+f"(d[mt][nt][0]), "+f"(d[mt][nt][1]),
                      "+f"(d[mt][nt][2]), "+f"(d[mt][nt][3])
                    : "r"(a0), "r"(a1), "r"(a2), "r"(a3),
                      "r"(bfr[nt][ks][0]), "r"(bfr[nt][ks][1]));
        }
    }
    __syncwarp();

    #pragma unroll
    for (int mt = 0; mt < MT; mt++) {
        int c = mt*16 + g;
        #pragma unroll
        for (int nt = 0; nt < 2; nt++) {
            int p0 = nt*8 + 2*t4;
            nf[w][p0  ][c  ] = __float2half(d[mt][nt][0]);
            nf[w][p0+1][c  ] = __float2half(d[mt][nt][1]);
            nf[w][p0  ][c+8] = __float2half(d[mt][nt][2]);
            nf[w][p0+1][c+8] = __float2half(d[mt][nt][3]);
        }
    }
    __syncwarp();
    constexpr int CH = P_ * CIN / 8;
    #pragma unroll
    for (int cid = lane; cid < CH; cid += 32) {
        int p = cid / (CIN/8), cc = cid % (CIN/8);
        uint4 v = *(const uint4*)&nf[w][p][cc*8];
        *(uint4*)(fk + (size_t)n*(P_*CIN) + cid*8) = v;
    }
}

// ================= fp16 tensor-core GEMM: BK=64, 4-stage cp.async, wait 2 ========
__device__ __forceinline__ void cpasync16(uint32_t dst, const void* src, bool valid) {
    int sz = valid ? 16 : 0;
    asm volatile("cp.async.cg.shared.global [%0], [%1], 16, %2;\n"
                 :: "r"(dst), "l"(src), "r"(sz));
}

template<int MF, int NF, bool LEAKY, bool CAT, bool OUTHALF, bool STATS>
__global__ __launch_bounds__(256)
void gemm_tc(const __half* __restrict__ A, const __half* __restrict__ Bt,
             void* __restrict__ Cv, int M, int N, int Kd,
             const int* __restrict__ upidx, const __half* __restrict__ Askip,
             int c_up, int c_skip, float* __restrict__ rowsum, int* __restrict__ gmaxp)
{
    constexpr int BM = MF * 64, BN = NF * 64;
    constexpr int AI = BM / 32;          // A 16B-chunks per thread per stage
    constexpr int BI = BN / 32;          // B chunks per thread per stage
    extern __shared__ __align__(16) __half dynsm[];
    __half* As = dynsm;                  // 4 stages of [BM][72]
    __half* Bs = dynsm + 4*BM*72;        // 4 stages of [BN][72]
    __shared__ float swm[8];

    const int bm = blockIdx.y * BM, bn = blockIdx.x * BN;
    const int tid  = threadIdx.x;
    const int warp = tid >> 5, lane = tid & 31;
    const int wm = warp >> 1, wn = warp & 1;
    const int g  = lane >> 2, tg = lane & 3;

    float c[MF][4*NF][4];
    #pragma unroll
    for (int i = 0; i < MF; i++)
        #pragma unroll
        for (int j = 0; j < 4*NF; j++) {
            c[i][j][0]=0.f; c[i][j][1]=0.f; c[i][j][2]=0.f; c[i][j][3]=0.f;
        }

    const int arow = tid >> 3;           // 0..31, + i*32
    const int akoff = (tid & 7) * 8;     // 0..56 halfs

    int ridx[AI];
    if (CAT) {
        #pragma unroll
        for (int i = 0; i < AI; i++) {
            int r = bm + arow + i * 32;
            ridx[i] = (r < M) ? upidx[r] : 0;
        }
    }

    const int nk = Kd >> 6;

    auto issue = [&](int s, int k0) {
        __half* Ast = As + s * (BM*72);
        #pragma unroll
        for (int i = 0; i < AI; i++) {
            int r = arow + i * 32;
            bool v = (bm + r) < M;
            int kc = k0 + akoff;
            const __half* src;
            if (CAT) {
                src = (kc < c_up) ? (A + (size_t)ridx[i] * c_up + kc)
                                  : (Askip + (size_t)(bm + r) * c_skip + (kc - c_up));
                if (!v) src = A;
            } else {
                src = v ? (A + (size_t)(bm + r) * Kd + kc) : A;
            }
            cpasync16((uint32_t)__cvta_generic_to_shared(&Ast[r*72 + akoff]), src, v);
        }
        __half* Bst = Bs + s * (BN*72);
        #pragma unroll
        for (int i = 0; i < BI; i++) {
            int r = arow + i * 32;
            bool v = (bn + r) < N;
            const __half* srcb = v ? (Bt + (size_t)(bn + r) * Kd + k0 + akoff) : Bt;
            cpasync16((uint32_t)__cvta_generic_to_shared(&Bst[r*72 + akoff]), srcb, v);
        }
        asm volatile("cp.async.commit_group;\n");
    };

    auto compute = [&](int s) {
        const __half* Ast = As + s * (BM*72);
        const __half* Bst = Bs + s * (BN*72);
        #pragma unroll
        for (int k0 = 0; k0 < 64; k0 += 16) {
            uint32_t a[MF][4], bf[4*NF][2];
            #pragma unroll
            for (int i = 0; i < MF; i++) {
                int r = wm * MF * 16 + i * 16 + g;
                a[i][0] = *(const uint32_t*)&Ast[r*72     + k0 + 2*tg    ];
                a[i][1] = *(const uint32_t*)&Ast[(r+8)*72 + k0 + 2*tg    ];
                a[i][2] = *(const uint32_t*)&Ast[r*72     + k0 + 2*tg + 8];
                a[i][3] = *(const uint32_t*)&Ast[(r+8)*72 + k0 + 2*tg + 8];
            }
            #pragma unroll
            for (int j = 0; j < 4*NF; j++) {
                int col = wn * NF * 32 + j * 8 + g;
                bf[j][0] = *(const uint32_t*)&Bst[col*72 + k0 + 2*tg    ];
                bf[j][1] = *(const uint32_t*)&Bst[col*72 + k0 + 2*tg + 8];
            }
            #pragma unroll
            for (int i = 0; i < MF; i++)
                #pragma unroll
                for (int j = 0; j < 4*NF; j++)
                    asm volatile(
                        "mma.sync.aligned.m16n8k16.row.col.f32.f16.f16.f32 "
                        "{%0,%1,%2,%3},{%4,%5,%6,%7},{%8,%9},{%0,%1,%2,%3};\n"
                        : "+f"(c[i][j][0]), "+f"(c[i][j][1]),
                          "+f"(c[i][j][2]), "+f"(c[i][j][3])
                        : "r"(a[i][0]), "r"(a[i][1]), "r"(a[i][2]), "r"(a[i][3]),
                          "r"(bf[j][0]), "r"(bf[j][1]));
        }
    };

    // 4-stage ring, up to 3 groups outstanding (wait_group 2).
    issue(0, 0);
    if (nk > 1) issue(1, 64);  else asm volatile("cp.async.commit_group;\n");
    if (nk > 2) issue(2, 128); else asm volatile("cp.async.commit_group;\n");
    int st = 0;
    for (int kt = 0; kt < nk; kt++) {
        asm volatile("cp.async.wait_group 2;\n");
        __syncthreads();
        compute(st);
        int nx = kt + 3;
        int ws = st + 3; if (ws >= 4) ws -= 4;
        if (nx < nk) issue(ws, nx << 6);
        else asm volatile("cp.async.commit_group;\n");
        if (++st == 4) st = 0;
    }

    __half* Ch = (__half*)Cv;
    float*  Cf = (float*)Cv;
    #pragma unroll
    for (int i = 0; i < MF; i++) {
        int r0 = bm + wm * MF * 16 + i * 16 + g;
        #pragma unroll
        for (int j = 0; j < 4*NF; j++) {
            int col = bn + wn * NF * 32 + j * 8 + 2 * tg;
            if (col < N) {
                if (r0 < M) {
                    float v0 = c[i][j][0], v1 = c[i][j][1];
                    if (LEAKY) { v0 = v0 > 0.f ? v0 : 0.1f*v0; v1 = v1 > 0.f ? v1 : 0.1f*v1; }
                    if (OUTHALF) *(__half2*)&Ch[(size_t)r0 * N + col] = __floats2half2_rn(v0, v1);
                    else { Cf[(size_t)r0 * N + col] = v0; Cf[(size_t)r0 * N + col + 1] = v1; }
                }
                if (r0 + 8 < M) {
                    float v2 = c[i][j][2], v3 = c[i][j][3];
                    if (LEAKY) { v2 = v2 > 0.f ? v2 : 0.1f*v2; v3 = v3 > 0.f ? v3 : 0.1f*v3; }
                    if (OUTHALF) *(__half2*)&Ch[(size_t)(r0+8) * N + col] = __floats2half2_rn(v2, v3);
                    else { Cf[(size_t)(r0+8) * N + col] = v2; Cf[(size_t)(r0+8) * N + col + 1] = v3; }
                }
            }
        }
    }

    if (STATS) {
        float wmax = 0.f;
        if (wn == 0) {
            #pragma unroll
            for (int i = 0; i < MF; i++) {
                float sl = 0.f, sh = 0.f, ml = 0.f, mh = 0.f;
                #pragma unroll
                for (int j = 0; j < 4*NF; j++) {
                    sl += c[i][j][0] + c[i][j][1];
                    sh += c[i][j][2] + c[i][j][3];
                    ml = fmaxf(ml, fmaxf(c[i][j][0], c[i][j][1]));
                    mh = fmaxf(mh, fmaxf(c[i][j][2], c[i][j][3]));
                }
                sl += __shfl_xor_sync(0xffffffffu, sl, 1);
                sl += __shfl_xor_sync(0xffffffffu, sl, 2);
                sh += __shfl_xor_sync(0xffffffffu, sh, 1);
                sh += __shfl_xor_sync(0xffffffffu, sh, 2);
                ml = fmaxf(ml, __shfl_xor_sync(0xffffffffu, ml, 1));
                ml = fmaxf(ml, __shfl_xor_sync(0xffffffffu, ml, 2));
                mh = fmaxf(mh, __shfl_xor_sync(0xffffffffu, mh, 1));
                mh = fmaxf(mh, __shfl_xor_sync(0xffffffffu, mh, 2));
                int r0 = bm + wm * MF * 16 + i * 16 + g;
                if (tg == 0) {
                    if (r0 < M)     rowsum[r0]     = sl;
                    if (r0 + 8 < M) rowsum[r0 + 8] = sh;
                }
                wmax = fmaxf(wmax, fmaxf(ml, mh));
            }
        }
        #pragma unroll
        for (int o = 16; o; o >>= 1)
            wmax = fmaxf(wmax, __shfl_xor_sync(0xffffffffu, wmax, o));
        if (lane == 0) swm[warp] = wmax;
        __syncthreads();
        if (tid == 0) {
            float bmv = swm[0];
            #pragma unroll
            for (int ww = 1; ww < 8; ww++) bmv = fmaxf(bmv, swm[ww]);
            atomicMax(gmaxp, __float_as_int(fmaxf(bmv, 0.f)));
        }
    }
}

// ---------------- detection head: float4 neighbor accumulation -------------------
__global__ void scores_kernel(const int* __restrict__ neigh, const float* __restrict__ ff,
                              const float* __restrict__ rowsum,
                              float* __restrict__ out_fnorm, float* __restrict__ out_scores)
{
    int warp = (blockIdx.x*blockDim.x + threadIdx.x) >> 5;
    int lane = threadIdx.x & 31;
    if (warp >= N0_) return;
    float fraw = ff[(size_t)warp*32 + lane];
    float s2 = fraw*fraw;
    #pragma unroll
    for (int o = 16; o; o >>= 1) s2 += __shfl_xor_sync(0xffffffffu, s2, o);
    float nrm = fmaxf(sqrtf(s2), 1e-12f);
    out_fnorm[(size_t)warp*32 + lane] = fraw / nrm;

    float inv = 1.0f / (__int_as_float(g_gmax) + 1e-6f);
    int myidx = neigh[(size_t)warp*32 + lane];

    int nz = (rowsum[myidx] != 0.f) ? 1 : 0;
    #pragma unroll
    for (int o = 16; o; o >>= 1) nz += __shfl_xor_sync(0xffffffffu, nz, o);
    float nnumf = (float)(nz < 1 ? 1 : nz);

    const int c4 = lane & 7, kg = lane >> 3;
    float4 sum4 = make_float4(0.f,0.f,0.f,0.f);
    float4 max4 = make_float4(-1e30f,-1e30f,-1e30f,-1e30f);
    #pragma unroll
    for (int i = 0; i < 8; i++) {
        int idx = __shfl_sync(0xffffffffu, myidx, i*4 + kg);
        float4 v = *(const float4*)(ff + (size_t)idx*32 + c4*4);
        sum4.x += v.x; sum4.y += v.y; sum4.z += v.z; sum4.w += v.w;
        max4.x = fmaxf(max4.x, v.x); max4.y = fmaxf(max4.y, v.y);
        max4.z = fmaxf(max4.z, v.z); max4.w = fmaxf(max4.w, v.w);
    }
    #pragma unroll
    for (int o = 8; o <= 16; o <<= 1) {
        sum4.x += __shfl_xor_sync(0xffffffffu, sum4.x, o);
        sum4.y += __shfl_xor_sync(0xffffffffu, sum4.y, o);
        sum4.z += __shfl_xor_sync(0xffffffffu, sum4.z, o);
        sum4.w += __shfl_xor_sync(0xffffffffu, sum4.w, o);
        max4.x = fmaxf(max4.x, __shfl_xor_sync(0xffffffffu, max4.x, o));
        max4.y = fmaxf(max4.y, __shfl_xor_sync(0xffffffffu, max4.y, o));
        max4.z = fmaxf(max4.z, __shfl_xor_sync(0xffffffffu, max4.z, o));
        max4.w = fmaxf(max4.w, __shfl_xor_sync(0xffffffffu, max4.w, o));
    }
    int src = lane >> 2;
    float sx = __shfl_sync(0xffffffffu, sum4.x, src);
    float sy = __shfl_sync(0xffffffffu, sum4.y, src);
    float sz = __shfl_sync(0xffffffffu, sum4.z, src);
    float sw = __shfl_sync(0xffffffffu, sum4.w, src);
    float mx = __shfl_sync(0xffffffffu, max4.x, src);
    float my = __shfl_sync(0xffffffffu, max4.y, src);
    float mz = __shfl_sync(0xffffffffu, max4.z, src);
    float mw = __shfl_sync(0xffffffffu, max4.w, src);
    int comp = lane & 3;
    float msum = (comp == 0) ? sx : (comp == 1) ? sy : (comp == 2) ? sz : sw;
    float mraw = (comp == 0) ? mx : (comp == 1) ? my : (comp == 2) ? mz : mw;

    float f = fraw * inv;
    float mean = msum * inv / nnumf;
    float nmax = mraw * inv;
    float x = f - mean;
    float lms = fmaxf(x, 0.f) + log1pf(expf(-fabsf(x)));
    float dmax = f;
    #pragma unroll
    for (int o = 16; o; o >>= 1) dmax = fmaxf(dmax, __shfl_xor_sync(0xffffffffu, dmax, o));
    float sc = lms * f / (1e-6f + dmax);
    float det = (f == nmax) ? 1.f : 0.f;
    #pragma unroll
    for (int o = 16; o; o >>= 1) {
        sc  = fmaxf(sc,  __shfl_xor_sync(0xffffffffu, sc, o));
        det = fmaxf(det, __shfl_xor_sync(0xffffffffu, det, o));
    }
    if (lane == 0) out_scores[warp] = sc * det;
}

// ---------------- launch ----------------------------------------------------------
extern "C" void kernel_launch(void* const* d_in, const int* in_sizes, int n_in,
                              void* d_out, int out_size)
{
    const float* features   = (const float*)d_in[0];
    const float* points0    = (const float*)d_in[1];
    const float* points1    = (const float*)d_in[2];
    const float* points2    = (const float*)d_in[3];
    const int*   neighbors0 = (const int*)d_in[4];
    const int*   neighbors1 = (const int*)d_in[5];
    const int*   neighbors2 = (const int*)d_in[6];
    const int*   pools0     = (const int*)d_in[7];
    const int*   pools1     = (const int*)d_in[8];
    const int*   upsamples0 = (const int*)d_in[9];
    const int*   upsamples1 = (const int*)d_in[10];
    const float* kpoints    = (const float*)d_in[11];
    const float* W1  = (const float*)d_in[12];
    const float* W2  = (const float*)d_in[13];
    const float* W3  = (const float*)d_in[14];
    const float* W4  = (const float*)d_in[15];
    const float* W5  = (const float*)d_in[16];
    const float* Wu1 = (const float*)d_in[17];
    const float* Wu2 = (const float*)d_in[18];
    float* out = (float*)d_out;

    __half *f1,*f2,*f3,*f4,*f5,*fk,*fu1,*wh;
    float *ff,*rowsum;
    int *gmaxp;
    cudaGetSymbolAddress((void**)&f1,  g_f1);
    cudaGetSymbolAddress((void**)&f2,  g_f2);
    cudaGetSymbolAddress((void**)&f3,  g_f3);
    cudaGetSymbolAddress((void**)&f4,  g_f4);
    cudaGetSymbolAddress((void**)&f5,  g_f5);
    cudaGetSymbolAddress((void**)&fk,  g_fk);
    cudaGetSymbolAddress((void**)&fu1, g_fu1);
    cudaGetSymbolAddress((void**)&wh,  g_wh);
    cudaGetSymbolAddress((void**)&ff,  g_ff);
    cudaGetSymbolAddress((void**)&rowsum, g_rowsum);
    cudaGetSymbolAddress((void**)&gmaxp,  g_gmax);

    // dynamic smem: 4 stages * (BM+BN)*72 halfs * 2B
    const int sm21 = 4*(128+ 64)*72*2;   // 110592
    const int sm22 = 4*(128+128)*72*2;   // 147456
    const int sm11 = 4*( 64+ 64)*72*2;   // 73728
    const int sm12 = 4*( 64+128)*72*2;   // 110592
    cudaFuncSetAttribute(gemm_tc<2,1,true,false,true,false>,  cudaFuncAttributeMaxDynamicSharedMemorySize, sm21);
    cudaFuncSetAttribute(gemm_tc<2,2,true,false,true,false>,  cudaFuncAttributeMaxDynamicSharedMemorySize, sm22);
    cudaFuncSetAttribute(gemm_tc<1,1,true,false,true,false>,  cudaFuncAttributeMaxDynamicSharedMemorySize, sm11);
    cudaFuncSetAttribute(gemm_tc<1,2,true,false,true,false>,  cudaFuncAttributeMaxDynamicSharedMemorySize, sm12);
    cudaFuncSetAttribute(gemm_tc<2,2,true,true,true,false>,   cudaFuncAttributeMaxDynamicSharedMemorySize, sm22);
    cudaFuncSetAttribute(gemm_tc<2,1,false,true,false,true>,  cudaFuncAttributeMaxDynamicSharedMemorySize, sm21);

    // ---- prep (all weight transposes + gmax reset, one launch) ----
    prep_kernel<<<954, 256>>>(W2, W3, W4, W5, Wu1, Wu2, wh);

    // ---- encoder ----
    conv1_kernel<<<N0_/4, 256>>>(points0, neighbors0, features, kpoints, W1, f1);

    gather_mma_kernel<64,8><<<N1_/8, 256>>>(points1, points0, pools0, f1, kpoints, 0.5f, fk, N1_);
    gemm_tc<2,1,true,false,true,false><<<dim3(1,(N1_+127)/128), 256, sm21>>>(fk, wh+WOFF_W2, f2, N1_, 64, 960, nullptr, nullptr, 0, 0, nullptr, nullptr);

    gather_mma_kernel<64,8><<<N1_/8, 256>>>(points1, points1, neighbors1, f2, kpoints, 1.0f, fk, N1_);
    gemm_tc<2,2,true,false,true,false><<<dim3(1,(N1_+127)/128), 256, sm22>>>(fk, wh+WOFF_W3, f3, N1_, 128, 960, nullptr, nullptr, 0, 0, nullptr, nullptr);

    gather_mma_kernel<128,4><<<(N2_+3)/4, 128>>>(points2, points1, pools1, f3, kpoints, 1.0f, fk, N2_);
    gemm_tc<1,1,true,false,true,false><<<dim3(2,(N2_+63)/64), 256, sm11>>>(fk, wh+WOFF_W4, f4, N2_, 128, 1920, nullptr, nullptr, 0, 0, nullptr, nullptr);

    gather_mma_kernel<128,4><<<(N2_+3)/4, 128>>>(points2, points2, neighbors2, f4, kpoints, 2.0f, fk, N2_);
    gemm_tc<1,2,true,false,true,false><<<dim3(2,(N2_+63)/64), 256, sm12>>>(fk, wh+WOFF_W5, f5, N2_, 256, 1920, nullptr, nullptr, 0, 0, nullptr, nullptr);

    // ---- decoder (concat fused into GEMM A-load) ----
    gemm_tc<2,2,true,true,true,false><<<dim3(1,(N1_+127)/128), 256, sm22>>>(f5, wh+WOFF_U1, fu1, N1_, 128, 384,
                                                                            upsamples1, f3, 256, 128, nullptr, nullptr);
    gemm_tc<2,1,false,true,false,true><<<dim3(1,(N0_+127)/128), 256, sm21>>>(fu1, wh+WOFF_U2, ff, N0_, 32, 192,
                                                                             upsamples0, f1, 128, 64, rowsum, gmaxp);

    // ---- detection head + outputs ----
    scores_kernel<<<(N0_ + 7)/8, 256>>>(neighbors0, ff, rowsum, out, out + (size_t)N0_*32);
}